// round 1
// baseline (speedup 1.0000x reference)
#include <cuda_runtime.h>
#include <cuda_bf16.h>

// Problem constants
#define BB 64
#define NN 4096
#define DD 256
#define KK 6
#define HH 64
#define CHUNKS 8
#define ROWS_PER_CHUNK (NN / CHUNKS)   // 512
#define WARPS_A 8
#define ROWS_PER_WARP (ROWS_PER_CHUNK / WARPS_A) // 64

// Device scratch (allocation-free rule: __device__ globals)
__device__ float g_qk[BB * KK * DD];            // per-iter query folded through Wk, pre-scaled
__device__ float g_partU[BB * CHUNKS * KK * DD]; // per-chunk partial weighted feature sums
__device__ float g_partS[BB * CHUNKS * KK];      // per-chunk partial attention mass

// ---------------------------------------------------------------------------
// Kernel I: slots = mu + sigma * noise  (written directly into d_out buffer)
// ---------------------------------------------------------------------------
__global__ void init_slots_kernel(float* __restrict__ slots,
                                  const float* __restrict__ noise,
                                  const float* __restrict__ mu,
                                  const float* __restrict__ sigma) {
    int i = blockIdx.x * blockDim.x + threadIdx.x;
    if (i < BB * KK * HH) {
        int h = i & (HH - 1);
        slots[i] = mu[h] + sigma[h] * noise[i];
    }
}

// ---------------------------------------------------------------------------
// Kernel P: per (b,k): s = LN(slots); q = Wq@s; qk = 0.125 * Wk^T @ q
// grid (KK, BB), block HH threads
// ---------------------------------------------------------------------------
__global__ void prep_kernel(const float* __restrict__ slots,
                            const float* __restrict__ ln_g,
                            const float* __restrict__ ln_b,
                            const float* __restrict__ Wq,
                            const float* __restrict__ Wk) {
    int k = blockIdx.x, b = blockIdx.y, t = threadIdx.x;
    __shared__ float s_s[HH];
    __shared__ float s_q[HH];

    float sv = slots[(b * KK + k) * HH + t];
    s_s[t] = sv;
    __syncthreads();

    float s1 = 0.f, s2 = 0.f;
#pragma unroll 8
    for (int i = 0; i < HH; i++) { float x = s_s[i]; s1 += x; s2 += x * x; }
    float mean = s1 * (1.f / HH);
    float var = s2 * (1.f / HH) - mean * mean;
    float rs = rsqrtf(var + 1e-5f);
    float sn = (sv - mean) * rs * ln_g[t] + ln_b[t];
    __syncthreads();
    s_s[t] = sn;
    __syncthreads();

    float q = 0.f;
#pragma unroll 8
    for (int h = 0; h < HH; h++) q += Wq[t * HH + h] * s_s[h];
    s_q[t] = q * 0.125f;  // scale = SLOT_DIM^-0.5 folded in here
    __syncthreads();

#pragma unroll
    for (int i = 0; i < 4; i++) {
        int d = t + i * HH;
        float acc = 0.f;
#pragma unroll 8
        for (int h = 0; h < HH; h++) acc += s_q[h] * Wk[h * DD + d];
        g_qk[(b * KK + k) * DD + d] = acc;
    }
}

// ---------------------------------------------------------------------------
// Kernel A (hot): streaming pass over features.
// grid (CHUNKS, BB), block 256 = 8 warps; each warp owns 64 rows.
// Per row: fused LN -> 6 dots with qk -> softmax over slots ->
//   accumulate a_k * f into per-lane register tiles; ordered block combine.
// ---------------------------------------------------------------------------
__global__ void __launch_bounds__(256, 1)
attn_kernel(const float* __restrict__ feat,
            const float* __restrict__ ln_g,
            const float* __restrict__ ln_b) {
    int b = blockIdx.y, chunk = blockIdx.x;
    int tid = threadIdx.x;
    int w = tid >> 5, lane = tid & 31;

    __shared__ float s_qk[KK * DD];
    __shared__ float s_acc[KK * DD];
    __shared__ float s_S[KK];

    for (int i = tid; i < KK * DD; i += 256) {
        s_qk[i] = g_qk[b * KK * DD + i];
        s_acc[i] = 0.f;
    }
    if (tid < KK) s_S[tid] = 0.f;
    __syncthreads();

    // lane's 8 feature columns: {4l..4l+3} and {128+4l..128+4l+3} (two float4s)
    int d0 = 4 * lane;
    int d1 = 128 + 4 * lane;

    float qk_r[KK][8];
    float g_r[8], b_r[8];
#pragma unroll
    for (int k = 0; k < KK; k++)
#pragma unroll
        for (int j = 0; j < 4; j++) {
            qk_r[k][j]     = s_qk[k * DD + d0 + j];
            qk_r[k][4 + j] = s_qk[k * DD + d1 + j];
        }
#pragma unroll
    for (int j = 0; j < 4; j++) {
        g_r[j] = ln_g[d0 + j]; g_r[4 + j] = ln_g[d1 + j];
        b_r[j] = ln_b[d0 + j]; b_r[4 + j] = ln_b[d1 + j];
    }

    float acc[KK][8];
    float accS[KK];
#pragma unroll
    for (int k = 0; k < KK; k++) {
        accS[k] = 0.f;
#pragma unroll
        for (int j = 0; j < 8; j++) acc[k][j] = 0.f;
    }

    const float* rp = feat + ((size_t)b * NN + (size_t)chunk * ROWS_PER_CHUNK
                              + (size_t)w * ROWS_PER_WARP) * DD;
    float4 fA = *reinterpret_cast<const float4*>(rp + d0);
    float4 fB = *reinterpret_cast<const float4*>(rp + d1);

    for (int r = 0; r < ROWS_PER_WARP; r++) {
        float f[8] = {fA.x, fA.y, fA.z, fA.w, fB.x, fB.y, fB.z, fB.w};
        const float* np = rp + DD;
        if (r < ROWS_PER_WARP - 1) {  // prefetch next row
            fA = *reinterpret_cast<const float4*>(np + d0);
            fB = *reinterpret_cast<const float4*>(np + d1);
        }
        rp = np;

        // LayerNorm statistics (warp reduce)
        float s1 = 0.f, s2 = 0.f;
#pragma unroll
        for (int j = 0; j < 8; j++) { s1 += f[j]; s2 += f[j] * f[j]; }
#pragma unroll
        for (int off = 16; off > 0; off >>= 1) {
            s1 += __shfl_xor_sync(0xFFFFFFFFu, s1, off);
            s2 += __shfl_xor_sync(0xFFFFFFFFu, s2, off);
        }
        float mean = s1 * (1.f / DD);
        float var = s2 * (1.f / DD) - mean * mean;
        float rstd = rsqrtf(var + 1e-5f);
#pragma unroll
        for (int j = 0; j < 8; j++) f[j] = (f[j] - mean) * rstd * g_r[j] + b_r[j];

        // 6 dot products with qk
        float dot[KK];
#pragma unroll
        for (int k = 0; k < KK; k++) {
            float d = 0.f;
#pragma unroll
            for (int j = 0; j < 8; j++) d += f[j] * qk_r[k][j];
            dot[k] = d;
        }
#pragma unroll
        for (int off = 16; off > 0; off >>= 1)
#pragma unroll
            for (int k = 0; k < KK; k++)
                dot[k] += __shfl_xor_sync(0xFFFFFFFFu, dot[k], off);

        // softmax over the 6 slots (all lanes redundantly)
        float mx = dot[0];
#pragma unroll
        for (int k = 1; k < KK; k++) mx = fmaxf(mx, dot[k]);
        float e[KK], se = 0.f;
#pragma unroll
        for (int k = 0; k < KK; k++) { e[k] = __expf(dot[k] - mx); se += e[k]; }
        float inv = 1.f / se;

        // weighted accumulation
#pragma unroll
        for (int k = 0; k < KK; k++) {
            float a = e[k] * inv;
            accS[k] += a;
#pragma unroll
            for (int j = 0; j < 8; j++) acc[k][j] += a * f[j];
        }
    }

    // ordered (deterministic) combine across the 8 warps
    for (int ww = 0; ww < WARPS_A; ww++) {
        if (w == ww) {
#pragma unroll
            for (int k = 0; k < KK; k++) {
#pragma unroll
                for (int j = 0; j < 4; j++) {
                    s_acc[k * DD + d0 + j] += acc[k][j];
                    s_acc[k * DD + d1 + j] += acc[k][4 + j];
                }
            }
            if (lane == 0)
#pragma unroll
                for (int k = 0; k < KK; k++) s_S[k] += accS[k];
        }
        __syncthreads();
    }

    float* pU = g_partU + ((size_t)(b * CHUNKS + chunk) * KK) * DD;
    for (int i = tid; i < KK * DD; i += 256) pU[i] = s_acc[i];
    if (tid < KK) g_partS[(b * CHUNKS + chunk) * KK + tid] = s_S[tid];
}

// ---------------------------------------------------------------------------
// Kernel C: per (b,k): reduce partials -> updates = Wv@U/(S+1e-8) ->
//           GRUCell -> LN -> MLP residual -> new slots
// grid (KK, BB), block HH threads
// ---------------------------------------------------------------------------
__global__ void update_kernel(float* __restrict__ slots,
                              const float* __restrict__ Wv,
                              const float* __restrict__ Wih,
                              const float* __restrict__ Whh,
                              const float* __restrict__ bih,
                              const float* __restrict__ bhh,
                              const float* __restrict__ lnm_g,
                              const float* __restrict__ lnm_b,
                              const float* __restrict__ W1,
                              const float* __restrict__ b1,
                              const float* __restrict__ W2,
                              const float* __restrict__ b2) {
    int k = blockIdx.x, b = blockIdx.y, t = threadIdx.x;
    __shared__ float U[DD];
    __shared__ float xv[HH];
    __shared__ float hp[HH];
    __shared__ float hn[HH];
    __shared__ float mm[HH];
    __shared__ float m1[2 * HH];

#pragma unroll
    for (int i = 0; i < 4; i++) {
        int d = t + i * HH;
        float u = 0.f;
#pragma unroll
        for (int c = 0; c < CHUNKS; c++)
            u += g_partU[((size_t)(b * CHUNKS + c) * KK + k) * DD + d];
        U[d] = u;
    }
    float S = 0.f;
#pragma unroll
    for (int c = 0; c < CHUNKS; c++) S += g_partS[(b * CHUNKS + c) * KK + k];
    float invS = 1.f / (S + 1e-8f);
    hp[t] = slots[(b * KK + k) * HH + t];
    __syncthreads();

    float acc = 0.f;
#pragma unroll 8
    for (int d = 0; d < DD; d++) acc += Wv[t * DD + d] * U[d];
    xv[t] = acc * invS;
    __syncthreads();

    // GRUCell (torch semantics; gate rows r,z,n at offsets 0,64,128)
    float gir = bih[t], giz = bih[HH + t], gin = bih[2 * HH + t];
    float ghr = bhh[t], ghz = bhh[HH + t], ghn = bhh[2 * HH + t];
#pragma unroll 8
    for (int j = 0; j < HH; j++) {
        float xj = xv[j], hj = hp[j];
        gir += Wih[t * HH + j] * xj;
        giz += Wih[(HH + t) * HH + j] * xj;
        gin += Wih[(2 * HH + t) * HH + j] * xj;
        ghr += Whh[t * HH + j] * hj;
        ghz += Whh[(HH + t) * HH + j] * hj;
        ghn += Whh[(2 * HH + t) * HH + j] * hj;
    }
    float r = 1.f / (1.f + __expf(-(gir + ghr)));
    float z = 1.f / (1.f + __expf(-(giz + ghz)));
    float n = tanhf(gin + r * ghn);
    float hv = (1.f - z) * n + z * hp[t];
    hn[t] = hv;
    __syncthreads();

    // LN over new slots
    float s1 = 0.f, s2 = 0.f;
#pragma unroll 8
    for (int i = 0; i < HH; i++) { float v = hn[i]; s1 += v; s2 += v * v; }
    float mean = s1 * (1.f / HH);
    float var = s2 * (1.f / HH) - mean * mean;
    float rs = rsqrtf(var + 1e-5f);
    mm[t] = (hv - mean) * rs * lnm_g[t] + lnm_b[t];
    __syncthreads();

    // MLP layer 1 (128 outputs)
#pragma unroll
    for (int i = 0; i < 2; i++) {
        int j = t + i * HH;
        float a = b1[j];
#pragma unroll 8
        for (int h = 0; h < HH; h++) a += W1[j * HH + h] * mm[h];
        m1[j] = fmaxf(a, 0.f);
    }
    __syncthreads();

    // MLP layer 2 + residual
    float a2 = b2[t];
#pragma unroll 8
    for (int j = 0; j < 2 * HH; j++) a2 += W2[t * 2 * HH + j] * m1[j];
    slots[(b * KK + k) * HH + t] = hv + a2;
}

// ---------------------------------------------------------------------------
extern "C" void kernel_launch(void* const* d_in, const int* in_sizes, int n_in,
                              void* d_out, int out_size) {
    const float* features  = (const float*)d_in[0];
    const float* slot_noise = (const float*)d_in[1];
    const float* slot_mu   = (const float*)d_in[2];
    const float* slot_sigma = (const float*)d_in[3];
    const float* ln_feat_g = (const float*)d_in[4];
    const float* ln_feat_b = (const float*)d_in[5];
    const float* ln_slot_g = (const float*)d_in[6];
    const float* ln_slot_b = (const float*)d_in[7];
    const float* ln_mlp_g  = (const float*)d_in[8];
    const float* ln_mlp_b  = (const float*)d_in[9];
    const float* Wk        = (const float*)d_in[10];
    const float* Wv        = (const float*)d_in[11];
    const float* Wq        = (const float*)d_in[12];
    const float* W_ih      = (const float*)d_in[13];
    const float* W_hh      = (const float*)d_in[14];
    const float* b_ih      = (const float*)d_in[15];
    const float* b_hh      = (const float*)d_in[16];
    const float* mlp_W1    = (const float*)d_in[17];
    const float* mlp_b1    = (const float*)d_in[18];
    const float* mlp_W2    = (const float*)d_in[19];
    const float* mlp_b2    = (const float*)d_in[20];

    float* slots = (float*)d_out;  // [B, K, H] lives in the output buffer

    init_slots_kernel<<<(BB * KK * HH + 255) / 256, 256>>>(slots, slot_noise,
                                                           slot_mu, slot_sigma);

    dim3 gridSmall(KK, BB);
    dim3 gridA(CHUNKS, BB);
    for (int it = 0; it < 3; it++) {
        prep_kernel<<<gridSmall, HH>>>(slots, ln_slot_g, ln_slot_b, Wq, Wk);
        attn_kernel<<<gridA, 256>>>(features, ln_feat_g, ln_feat_b);
        update_kernel<<<gridSmall, HH>>>(slots, Wv, W_ih, W_hh, b_ih, b_hh,
                                         ln_mlp_g, ln_mlp_b, mlp_W1, mlp_b1,
                                         mlp_W2, mlp_b2);
    }
}

// round 2
// speedup vs baseline: 1.4749x; 1.4749x over previous
#include <cuda_runtime.h>
#include <cuda_fp16.h>

// Problem constants
#define BB 64
#define NN 4096
#define DD 256
#define KK 6
#define HH 64
#define CHUNKS 8
#define ROWS_PER_CHUNK (NN / CHUNKS)   // 512
#define WARPS_A 8
#define ROWS_PER_WARP (ROWS_PER_CHUNK / WARPS_A) // 64

// Device scratch (allocation-free rule: __device__ globals)
__device__ __half g_fh[(size_t)BB * NN * DD];    // LN(features) in fp16 (128 MB)
__device__ float g_qk[BB * KK * DD];             // query folded through Wk, pre-scaled
__device__ float g_partU[BB * CHUNKS * KK * DD]; // per-chunk partial weighted feature sums
__device__ float g_partS[BB * CHUNKS * KK];      // per-chunk partial attention mass

// ---------------------------------------------------------------------------
// Kernel I: slots = mu + sigma * noise  (written directly into d_out buffer)
// ---------------------------------------------------------------------------
__global__ void init_slots_kernel(float* __restrict__ slots,
                                  const float* __restrict__ noise,
                                  const float* __restrict__ mu,
                                  const float* __restrict__ sigma) {
    int i = blockIdx.x * blockDim.x + threadIdx.x;
    if (i < BB * KK * HH) {
        int h = i & (HH - 1);
        slots[i] = mu[h] + sigma[h] * noise[i];
    }
}

// ---------------------------------------------------------------------------
// Kernel LN: one-time LN(features) -> fp16. One warp per row of 256.
// grid = B*N/8 blocks of 256 threads (8 warps).
// ---------------------------------------------------------------------------
__global__ void __launch_bounds__(256)
ln_feat_kernel(const float* __restrict__ feat,
               const float* __restrict__ g,
               const float* __restrict__ bvec) {
    int row = blockIdx.x * 8 + (threadIdx.x >> 5);
    int lane = threadIdx.x & 31;
    const float* rp = feat + (size_t)row * DD + 8 * lane;
    float4 a = ((const float4*)rp)[0];
    float4 c = ((const float4*)rp)[1];
    float f[8] = {a.x, a.y, a.z, a.w, c.x, c.y, c.z, c.w};

    float s1 = 0.f, s2 = 0.f;
#pragma unroll
    for (int j = 0; j < 8; j++) { s1 += f[j]; s2 += f[j] * f[j]; }
#pragma unroll
    for (int off = 16; off > 0; off >>= 1) {
        s1 += __shfl_xor_sync(0xFFFFFFFFu, s1, off);
        s2 += __shfl_xor_sync(0xFFFFFFFFu, s2, off);
    }
    float mean = s1 * (1.f / DD);
    float var = s2 * (1.f / DD) - mean * mean;
    float rstd = rsqrtf(var + 1e-5f);

    float4 ga = ((const float4*)(g + 8 * lane))[0];
    float4 gc = ((const float4*)(g + 8 * lane))[1];
    float4 ba = ((const float4*)(bvec + 8 * lane))[0];
    float4 bc = ((const float4*)(bvec + 8 * lane))[1];
    float gg[8] = {ga.x, ga.y, ga.z, ga.w, gc.x, gc.y, gc.z, gc.w};
    float bb[8] = {ba.x, ba.y, ba.z, ba.w, bc.x, bc.y, bc.z, bc.w};
#pragma unroll
    for (int j = 0; j < 8; j++) f[j] = (f[j] - mean) * rstd * gg[j] + bb[j];

    __half2 h[4];
#pragma unroll
    for (int j = 0; j < 4; j++)
        h[j] = __float22half2_rn(make_float2(f[2 * j], f[2 * j + 1]));
    *(uint4*)(g_fh + (size_t)row * DD + 8 * lane) = *(uint4*)h;
}

// ---------------------------------------------------------------------------
// Kernel P: per (b,k): s = LN(slots); q = Wq@s; qk = 0.125 * Wk^T @ q
// grid (KK, BB), block 256
// ---------------------------------------------------------------------------
__global__ void __launch_bounds__(256)
prep_kernel(const float* __restrict__ slots,
            const float* __restrict__ ln_g,
            const float* __restrict__ ln_b,
            const float* __restrict__ Wq,
            const float* __restrict__ Wk) {
    int k = blockIdx.x, b = blockIdx.y, t = threadIdx.x;
    __shared__ __align__(16) float s_s[HH];
    __shared__ __align__(16) float s_q[HH];
    __shared__ float s_st[2];

    if (t < HH) s_s[t] = slots[(b * KK + k) * HH + t];
    __syncthreads();

    if (t < 32) {
        float a = s_s[t], c = s_s[32 + t];
        float s1 = a + c, s2 = a * a + c * c;
#pragma unroll
        for (int off = 16; off > 0; off >>= 1) {
            s1 += __shfl_xor_sync(0xFFFFFFFFu, s1, off);
            s2 += __shfl_xor_sync(0xFFFFFFFFu, s2, off);
        }
        if (t == 0) {
            float mean = s1 * (1.f / HH);
            float var = s2 * (1.f / HH) - mean * mean;
            s_st[0] = mean;
            s_st[1] = rsqrtf(var + 1e-5f);
        }
    }
    __syncthreads();
    if (t < HH) s_s[t] = (s_s[t] - s_st[0]) * s_st[1] * ln_g[t] + ln_b[t];
    __syncthreads();

    // q = Wq @ s, 4 threads per output, pre-scaled by 0.125
    {
        int o = t >> 2, q4 = t & 3;
        const float4* w = (const float4*)(Wq + o * HH + q4 * 16);
        const float4* sv = (const float4*)(s_s + q4 * 16);
        float acc = 0.f;
#pragma unroll
        for (int i = 0; i < 4; i++) {
            float4 w4 = w[i], s4 = sv[i];
            acc += w4.x * s4.x + w4.y * s4.y + w4.z * s4.z + w4.w * s4.w;
        }
        acc += __shfl_xor_sync(0xFFFFFFFFu, acc, 1);
        acc += __shfl_xor_sync(0xFFFFFFFFu, acc, 2);
        if (q4 == 0) s_q[o] = acc * 0.125f;
    }
    __syncthreads();

    // qk[d] = sum_h q[h] * Wk[h][d], one output per thread, coalesced over d
    {
        float a0 = 0.f, a1 = 0.f, a2 = 0.f, a3 = 0.f;
#pragma unroll
        for (int h = 0; h < HH; h += 4) {
            a0 += s_q[h]     * Wk[(h)     * DD + t];
            a1 += s_q[h + 1] * Wk[(h + 1) * DD + t];
            a2 += s_q[h + 2] * Wk[(h + 2) * DD + t];
            a3 += s_q[h + 3] * Wk[(h + 3) * DD + t];
        }
        g_qk[(b * KK + k) * DD + t] = (a0 + a1) + (a2 + a3);
    }
}

// ---------------------------------------------------------------------------
// Kernel A (hot): streaming pass over fp16 normalized features, 2 rows/step.
// grid (CHUNKS, BB), block 256 = 8 warps; each warp owns 64 rows.
// ---------------------------------------------------------------------------
__global__ void __launch_bounds__(256, 1)
attn_kernel() {
    int b = blockIdx.y, chunk = blockIdx.x;
    int tid = threadIdx.x;
    int w = tid >> 5, lane = tid & 31;

    __shared__ float s_qk[KK * DD];
    __shared__ float s_acc[KK * DD];
    __shared__ float s_S[KK];

    for (int i = tid; i < KK * DD; i += 256) {
        s_qk[i] = g_qk[b * KK * DD + i];
        s_acc[i] = 0.f;
    }
    if (tid < KK) s_S[tid] = 0.f;
    __syncthreads();

    int c0 = 8 * lane;  // lane's 8 contiguous feature columns

    float qk_r[KK][8];
#pragma unroll
    for (int k = 0; k < KK; k++)
#pragma unroll
        for (int j = 0; j < 8; j++) qk_r[k][j] = s_qk[k * DD + c0 + j];

    float acc[KK][8];
    float accS[KK];
#pragma unroll
    for (int k = 0; k < KK; k++) {
        accS[k] = 0.f;
#pragma unroll
        for (int j = 0; j < 8; j++) acc[k][j] = 0.f;
    }

    const __half* rp = g_fh + ((size_t)b * NN + (size_t)chunk * ROWS_PER_CHUNK
                               + (size_t)w * ROWS_PER_WARP) * DD + c0;
    uint4 u0 = *(const uint4*)rp;
    uint4 u1 = *(const uint4*)(rp + DD);

    for (int r = 0; r < ROWS_PER_WARP / 2; r++) {
        float f0[8], f1[8];
#pragma unroll
        for (int j = 0; j < 4; j++) {
            float2 p0 = __half22float2(((const __half2*)&u0)[j]);
            float2 p1 = __half22float2(((const __half2*)&u1)[j]);
            f0[2 * j] = p0.x; f0[2 * j + 1] = p0.y;
            f1[2 * j] = p1.x; f1[2 * j + 1] = p1.y;
        }
        if (r < ROWS_PER_WARP / 2 - 1) {  // prefetch next row pair
            u0 = *(const uint4*)(rp + 2 * DD);
            u1 = *(const uint4*)(rp + 3 * DD);
        }
        rp += 2 * DD;

        // 6 dots per row, two independent rows
        float d0[KK], d1[KK];
#pragma unroll
        for (int k = 0; k < KK; k++) {
            float a0 = 0.f, a1 = 0.f;
#pragma unroll
            for (int j = 0; j < 8; j++) {
                a0 += f0[j] * qk_r[k][j];
                a1 += f1[j] * qk_r[k][j];
            }
            d0[k] = a0; d1[k] = a1;
        }
#pragma unroll
        for (int off = 16; off > 0; off >>= 1) {
#pragma unroll
            for (int k = 0; k < KK; k++) {
                d0[k] += __shfl_xor_sync(0xFFFFFFFFu, d0[k], off);
                d1[k] += __shfl_xor_sync(0xFFFFFFFFu, d1[k], off);
            }
        }

        // softmax over the 6 slots (redundant in all lanes), both rows
        float mx0 = d0[0], mx1 = d1[0];
#pragma unroll
        for (int k = 1; k < KK; k++) {
            mx0 = fmaxf(mx0, d0[k]);
            mx1 = fmaxf(mx1, d1[k]);
        }
        float e0[KK], e1[KK], se0 = 0.f, se1 = 0.f;
#pragma unroll
        for (int k = 0; k < KK; k++) {
            e0[k] = __expf(d0[k] - mx0); se0 += e0[k];
            e1[k] = __expf(d1[k] - mx1); se1 += e1[k];
        }
        float inv0 = 1.f / se0, inv1 = 1.f / se1;

#pragma unroll
        for (int k = 0; k < KK; k++) {
            float a0 = e0[k] * inv0, a1 = e1[k] * inv1;
            accS[k] += a0 + a1;
#pragma unroll
            for (int j = 0; j < 8; j++)
                acc[k][j] += a0 * f0[j] + a1 * f1[j];
        }
    }

    // ordered (deterministic) combine across the 8 warps
    for (int ww = 0; ww < WARPS_A; ww++) {
        if (w == ww) {
#pragma unroll
            for (int k = 0; k < KK; k++) {
#pragma unroll
                for (int j = 0; j < 8; j++)
                    s_acc[k * DD + c0 + j] += acc[k][j];
            }
            if (lane == 0)
#pragma unroll
                for (int k = 0; k < KK; k++) s_S[k] += accS[k];
        }
        __syncthreads();
    }

    float* pU = g_partU + ((size_t)(b * CHUNKS + chunk) * KK) * DD;
    for (int i = tid; i < KK * DD; i += 256) pU[i] = s_acc[i];
    if (tid < KK) g_partS[(b * CHUNKS + chunk) * KK + tid] = s_S[tid];
}

// ---------------------------------------------------------------------------
// Kernel C: per (b,k): reduce partials -> updates = Wv@U/(S+1e-8) ->
//           GRUCell -> LN -> MLP residual -> new slots.  block = 256.
// ---------------------------------------------------------------------------
__global__ void __launch_bounds__(256)
update_kernel(float* __restrict__ slots,
              const float* __restrict__ Wv,
              const float* __restrict__ Wih,
              const float* __restrict__ Whh,
              const float* __restrict__ bih,
              const float* __restrict__ bhh,
              const float* __restrict__ lnm_g,
              const float* __restrict__ lnm_b,
              const float* __restrict__ W1,
              const float* __restrict__ b1,
              const float* __restrict__ W2,
              const float* __restrict__ b2) {
    int k = blockIdx.x, b = blockIdx.y, t = threadIdx.x;
    __shared__ __align__(16) float U[DD];
    __shared__ __align__(16) float s_xv[HH];
    __shared__ __align__(16) float s_hp[HH];
    __shared__ float s_grz[2 * HH];
    __shared__ float s_gin[HH], s_ghn[HH];
    __shared__ float s_hn[HH];
    __shared__ __align__(16) float s_mm[HH];
    __shared__ __align__(16) float s_m1[2 * HH];
    __shared__ float s_st[4];  // invS, mean, rstd

    // Phase A: reduce chunk partials (fixed order -> deterministic)
    {
        float u = 0.f;
#pragma unroll
        for (int c = 0; c < CHUNKS; c++)
            u += g_partU[((size_t)(b * CHUNKS + c) * KK + k) * DD + t];
        U[t] = u;
    }
    if (t < 32) {
        float S = (t < CHUNKS) ? g_partS[(b * CHUNKS + t) * KK + k] : 0.f;
#pragma unroll
        for (int off = 4; off > 0; off >>= 1)
            S += __shfl_xor_sync(0xFFFFFFFFu, S, off);
        if (t == 0) s_st[0] = 1.f / (S + 1e-8f);
    }
    if (t >= 64 && t < 128) s_hp[t - 64] = slots[(b * KK + k) * HH + (t - 64)];
    __syncthreads();

    // Phase B: xv = (Wv @ U) * invS   (4 threads per output)
    {
        int o = t >> 2, q = t & 3;
        const float4* wv = (const float4*)(Wv + o * DD + q * 64);
        const float4* uu = (const float4*)(U + q * 64);
        float a0 = 0.f, a1 = 0.f;
#pragma unroll
        for (int i = 0; i < 16; i++) {
            float4 w4 = wv[i], u4 = uu[i];
            a0 += w4.x * u4.x + w4.z * u4.z;
            a1 += w4.y * u4.y + w4.w * u4.w;
        }
        float acc = a0 + a1;
        acc += __shfl_xor_sync(0xFFFFFFFFu, acc, 1);
        acc += __shfl_xor_sync(0xFFFFFFFFu, acc, 2);
        if (q == 0) s_xv[o] = acc * s_st[0];
    }
    __syncthreads();

    // Phase C: GRU gate GEMVs (one thread per gate-output; 192 active)
    if (t < 192) {
        int gate = t >> 6, idx = t & 63;
        const float4* wi = (const float4*)(Wih + t * HH);
        const float4* wh = (const float4*)(Whh + t * HH);
        const float4* xv4 = (const float4*)s_xv;
        const float4* hp4 = (const float4*)s_hp;
        float gi = bih[t], gh = bhh[t];
#pragma unroll
        for (int i = 0; i < 16; i++) {
            float4 w4 = wi[i], x4 = xv4[i];
            gi += w4.x * x4.x + w4.y * x4.y + w4.z * x4.z + w4.w * x4.w;
            float4 v4 = wh[i], h4 = hp4[i];
            gh += v4.x * h4.x + v4.y * h4.y + v4.z * h4.z + v4.w * h4.w;
        }
        if (gate < 2) s_grz[t] = gi + gh;
        else { s_gin[idx] = gi; s_ghn[idx] = gh; }
    }
    __syncthreads();

    // Phase D: gate nonlinearity + h update, then LN stats
    if (t < 64) {
        float r = 1.f / (1.f + __expf(-s_grz[t]));
        float z = 1.f / (1.f + __expf(-s_grz[64 + t]));
        float n = tanhf(s_gin[t] + r * s_ghn[t]);
        s_hn[t] = (1.f - z) * n + z * s_hp[t];
    }
    __syncthreads();
    if (t < 32) {
        float a = s_hn[t], c = s_hn[32 + t];
        float s1 = a + c, s2 = a * a + c * c;
#pragma unroll
        for (int off = 16; off > 0; off >>= 1) {
            s1 += __shfl_xor_sync(0xFFFFFFFFu, s1, off);
            s2 += __shfl_xor_sync(0xFFFFFFFFu, s2, off);
        }
        if (t == 0) {
            float mean = s1 * (1.f / HH);
            float var = s2 * (1.f / HH) - mean * mean;
            s_st[1] = mean;
            s_st[2] = rsqrtf(var + 1e-5f);
        }
    }
    __syncthreads();
    if (t < 64) s_mm[t] = (s_hn[t] - s_st[1]) * s_st[2] * lnm_g[t] + lnm_b[t];
    __syncthreads();

    // Phase E: MLP layer 1 (2 threads per output)
    {
        int o = t >> 1, hf = t & 1;
        const float4* w1 = (const float4*)(W1 + o * HH + hf * 32);
        const float4* mm4 = (const float4*)(s_mm + hf * 32);
        float acc = 0.f;
#pragma unroll
        for (int i = 0; i < 8; i++) {
            float4 w4 = w1[i], m4 = mm4[i];
            acc += w4.x * m4.x + w4.y * m4.y + w4.z * m4.z + w4.w * m4.w;
        }
        acc += __shfl_xor_sync(0xFFFFFFFFu, acc, 1);
        if (hf == 0) s_m1[o] = fmaxf(acc + b1[o], 0.f);
    }
    __syncthreads();

    // Phase F: MLP layer 2 + residual (4 threads per output)
    {
        int o = t >> 2, q = t & 3;
        const float4* w2 = (const float4*)(W2 + o * 2 * HH + q * 32);
        const float4* m14 = (const float4*)(s_m1 + q * 32);
        float acc = 0.f;
#pragma unroll
        for (int i = 0; i < 8; i++) {
            float4 w4 = w2[i], m4 = m14[i];
            acc += w4.x * m4.x + w4.y * m4.y + w4.z * m4.z + w4.w * m4.w;
        }
        acc += __shfl_xor_sync(0xFFFFFFFFu, acc, 1);
        acc += __shfl_xor_sync(0xFFFFFFFFu, acc, 2);
        if (q == 0) slots[(b * KK + k) * HH + o] = s_hn[o] + acc + b2[o];
    }
}

// ---------------------------------------------------------------------------
extern "C" void kernel_launch(void* const* d_in, const int* in_sizes, int n_in,
                              void* d_out, int out_size) {
    const float* features   = (const float*)d_in[0];
    const float* slot_noise = (const float*)d_in[1];
    const float* slot_mu    = (const float*)d_in[2];
    const float* slot_sigma = (const float*)d_in[3];
    const float* ln_feat_g  = (const float*)d_in[4];
    const float* ln_feat_b  = (const float*)d_in[5];
    const float* ln_slot_g  = (const float*)d_in[6];
    const float* ln_slot_b  = (const float*)d_in[7];
    const float* ln_mlp_g   = (const float*)d_in[8];
    const float* ln_mlp_b   = (const float*)d_in[9];
    const float* Wk         = (const float*)d_in[10];
    const float* Wv         = (const float*)d_in[11];
    const float* Wq         = (const float*)d_in[12];
    const float* W_ih       = (const float*)d_in[13];
    const float* W_hh       = (const float*)d_in[14];
    const float* b_ih       = (const float*)d_in[15];
    const float* b_hh       = (const float*)d_in[16];
    const float* mlp_W1     = (const float*)d_in[17];
    const float* mlp_b1     = (const float*)d_in[18];
    const float* mlp_W2     = (const float*)d_in[19];
    const float* mlp_b2     = (const float*)d_in[20];

    float* slots = (float*)d_out;  // [B, K, H] lives in the output buffer

    init_slots_kernel<<<(BB * KK * HH + 255) / 256, 256>>>(slots, slot_noise,
                                                           slot_mu, slot_sigma);
    ln_feat_kernel<<<BB * NN / 8, 256>>>(features, ln_feat_g, ln_feat_b);

    dim3 gridSmall(KK, BB);
    dim3 gridA(CHUNKS, BB);
    for (int it = 0; it < 3; it++) {
        prep_kernel<<<gridSmall, 256>>>(slots, ln_slot_g, ln_slot_b, Wq, Wk);
        attn_kernel<<<gridA, 256>>>();
        update_kernel<<<gridSmall, 256>>>(slots, Wv, W_ih, W_hh, b_ih, b_hh,
                                          ln_mlp_g, ln_mlp_b, mlp_W1, mlp_b1,
                                          mlp_W2, mlp_b2);
    }
}

// round 3
// speedup vs baseline: 2.3490x; 1.5927x over previous
#include <cuda_runtime.h>
#include <cuda_fp16.h>

// Problem constants
#define BB 64
#define NN 4096
#define DD 256
#define KK 6
#define HH 64
#define CHUNKS 16
#define ROWS_A (NN / CHUNKS)     // 256 rows per block
#define BATCH 64
#define NBATCH (ROWS_A / BATCH)  // 4

// Device scratch (allocation-free rule: __device__ globals)
__device__ __half g_fh[(size_t)BB * NN * DD];     // LN(features) in fp16 (128 MB)
__device__ float g_qk[BB * KK * DD];              // query folded through Wk, pre-scaled
__device__ float g_partU[BB * CHUNKS * KK * DD];  // per-chunk partial weighted sums
__device__ float g_partS[BB * CHUNKS * KK];       // per-chunk partial attention mass

// ---------------------------------------------------------------------------
// f32x2 packed-math helpers (Blackwell FFMA2 via PTX)
// ---------------------------------------------------------------------------
__device__ __forceinline__ unsigned long long pk2(float x, float y) {
    unsigned long long r;
    asm("mov.b64 %0, {%1, %2};" : "=l"(r) : "f"(x), "f"(y));
    return r;
}
__device__ __forceinline__ unsigned long long pkf2(float2 v) { return pk2(v.x, v.y); }
__device__ __forceinline__ void fma2(unsigned long long& d, unsigned long long a,
                                     unsigned long long b) {
    asm("fma.rn.f32x2 %0, %1, %2, %0;" : "+l"(d) : "l"(a), "l"(b));
}
__device__ __forceinline__ float2 upk2(unsigned long long v) {
    float2 f;
    asm("mov.b64 {%0, %1}, %2;" : "=f"(f.x), "=f"(f.y) : "l"(v));
    return f;
}

// ---------------------------------------------------------------------------
// Kernel I: slots = mu + sigma * noise  (written directly into d_out buffer)
// ---------------------------------------------------------------------------
__global__ void init_slots_kernel(float* __restrict__ slots,
                                  const float* __restrict__ noise,
                                  const float* __restrict__ mu,
                                  const float* __restrict__ sigma) {
    int i = blockIdx.x * blockDim.x + threadIdx.x;
    if (i < BB * KK * HH) {
        int h = i & (HH - 1);
        slots[i] = mu[h] + sigma[h] * noise[i];
    }
}

// ---------------------------------------------------------------------------
// Kernel LN: one-time LN(features) -> fp16. One warp per row of 256.
// ---------------------------------------------------------------------------
__global__ void __launch_bounds__(256)
ln_feat_kernel(const float* __restrict__ feat,
               const float* __restrict__ g,
               const float* __restrict__ bvec) {
    int row = blockIdx.x * 8 + (threadIdx.x >> 5);
    int lane = threadIdx.x & 31;
    const float* rp = feat + (size_t)row * DD + 8 * lane;
    float4 a = ((const float4*)rp)[0];
    float4 c = ((const float4*)rp)[1];
    float f[8] = {a.x, a.y, a.z, a.w, c.x, c.y, c.z, c.w};

    float s1 = 0.f, s2 = 0.f;
#pragma unroll
    for (int j = 0; j < 8; j++) { s1 += f[j]; s2 += f[j] * f[j]; }
#pragma unroll
    for (int off = 16; off > 0; off >>= 1) {
        s1 += __shfl_xor_sync(0xFFFFFFFFu, s1, off);
        s2 += __shfl_xor_sync(0xFFFFFFFFu, s2, off);
    }
    float mean = s1 * (1.f / DD);
    float var = s2 * (1.f / DD) - mean * mean;
    float rstd = rsqrtf(var + 1e-5f);

    float4 ga = ((const float4*)(g + 8 * lane))[0];
    float4 gc = ((const float4*)(g + 8 * lane))[1];
    float4 ba = ((const float4*)(bvec + 8 * lane))[0];
    float4 bc = ((const float4*)(bvec + 8 * lane))[1];
    float gg[8] = {ga.x, ga.y, ga.z, ga.w, gc.x, gc.y, gc.z, gc.w};
    float bb[8] = {ba.x, ba.y, ba.z, ba.w, bc.x, bc.y, bc.z, bc.w};
#pragma unroll
    for (int j = 0; j < 8; j++) f[j] = (f[j] - mean) * rstd * gg[j] + bb[j];

    __half2 h[4];
#pragma unroll
    for (int j = 0; j < 4; j++)
        h[j] = __float22half2_rn(make_float2(f[2 * j], f[2 * j + 1]));
    *(uint4*)(g_fh + (size_t)row * DD + 8 * lane) = *(uint4*)h;
}

// ---------------------------------------------------------------------------
// Kernel P: per (b,k): s = LN(slots); q = Wq@s; qk = 0.125 * Wk^T @ q
// grid (KK, BB), block 256
// ---------------------------------------------------------------------------
__global__ void __launch_bounds__(256)
prep_kernel(const float* __restrict__ slots,
            const float* __restrict__ ln_g,
            const float* __restrict__ ln_b,
            const float* __restrict__ Wq,
            const float* __restrict__ Wk) {
    int k = blockIdx.x, b = blockIdx.y, t = threadIdx.x;
    __shared__ __align__(16) float s_s[HH];
    __shared__ __align__(16) float s_q[HH];
    __shared__ float s_st[2];

    if (t < HH) s_s[t] = slots[(b * KK + k) * HH + t];
    __syncthreads();

    if (t < 32) {
        float a = s_s[t], c = s_s[32 + t];
        float s1 = a + c, s2 = a * a + c * c;
#pragma unroll
        for (int off = 16; off > 0; off >>= 1) {
            s1 += __shfl_xor_sync(0xFFFFFFFFu, s1, off);
            s2 += __shfl_xor_sync(0xFFFFFFFFu, s2, off);
        }
        if (t == 0) {
            float mean = s1 * (1.f / HH);
            float var = s2 * (1.f / HH) - mean * mean;
            s_st[0] = mean;
            s_st[1] = rsqrtf(var + 1e-5f);
        }
    }
    __syncthreads();
    if (t < HH) s_s[t] = (s_s[t] - s_st[0]) * s_st[1] * ln_g[t] + ln_b[t];
    __syncthreads();

    {
        int o = t >> 2, q4 = t & 3;
        const float4* w = (const float4*)(Wq + o * HH + q4 * 16);
        const float4* sv = (const float4*)(s_s + q4 * 16);
        float acc = 0.f;
#pragma unroll
        for (int i = 0; i < 4; i++) {
            float4 w4 = w[i], s4 = sv[i];
            acc += w4.x * s4.x + w4.y * s4.y + w4.z * s4.z + w4.w * s4.w;
        }
        acc += __shfl_xor_sync(0xFFFFFFFFu, acc, 1);
        acc += __shfl_xor_sync(0xFFFFFFFFu, acc, 2);
        if (q4 == 0) s_q[o] = acc * 0.125f;
    }
    __syncthreads();

    {
        float a0 = 0.f, a1 = 0.f, a2 = 0.f, a3 = 0.f;
#pragma unroll
        for (int h = 0; h < HH; h += 4) {
            a0 += s_q[h]     * Wk[(h)     * DD + t];
            a1 += s_q[h + 1] * Wk[(h + 1) * DD + t];
            a2 += s_q[h + 2] * Wk[(h + 2) * DD + t];
            a3 += s_q[h + 3] * Wk[(h + 3) * DD + t];
        }
        g_qk[(b * KK + k) * DD + t] = (a0 + a1) + (a2 + a3);
    }
}

// ---------------------------------------------------------------------------
// Kernel A (hot): smem-staged, shuffle-free attention streaming pass.
// grid (CHUNKS, BB), block 256 threads (8 warps). 256 rows/block,
// 4 double-buffered batches of 64 rows via cp.async.
// smem layout (dynamic, ~85.6 KB):
//   s_f   : 2 x [64][256] fp16, 16B-chunk XOR-swizzled   (65536 B)
//   s_qk  : [6][256] f32                                  (6144 B)
//   s_dot : [4][6][64] f32                                (6144 B)
//   s_a   : [64][6] f32                                   (1536 B)
//   s_U   : [6][256] f32                                  (6144 B)
//   s_Sp  : [2][6] f32                                    (48 B)
// ---------------------------------------------------------------------------
#define SMEM_F_BYTES (2 * BATCH * DD * 2)
#define ATTN_SMEM (SMEM_F_BYTES + (KK*DD + 4*KK*BATCH + BATCH*KK + KK*DD + 12) * 4)

__device__ __forceinline__ void issue_batch(const __half* gbase, int nb,
                                            char* smem, int tid) {
    const char* g = (const char*)(gbase + (size_t)nb * BATCH * DD);
    unsigned sbase = (unsigned)__cvta_generic_to_shared(smem) +
                     (nb & 1) * (BATCH * DD * 2);
#pragma unroll
    for (int it = 0; it < 8; it++) {
        int idx = tid + it * 256;
        int row = idx >> 5, j = idx & 31;
        unsigned dst = sbase + row * 512 + ((j ^ (row & 7)) << 4);
        const char* src = g + row * 512 + j * 16;
        asm volatile("cp.async.ca.shared.global [%0], [%1], 16;\n"
                     :: "r"(dst), "l"(src));
    }
    asm volatile("cp.async.commit_group;\n");
}

__global__ void __launch_bounds__(256, 2)
attn_kernel() {
    extern __shared__ __align__(16) char smem[];
    __half* s_f  = (__half*)smem;
    float* s_qk  = (float*)(smem + SMEM_F_BYTES);
    float* s_dot = s_qk + KK * DD;
    float* s_a   = s_dot + 4 * KK * BATCH;
    float* s_U   = s_a + BATCH * KK;
    float* s_Sp  = s_U + KK * DD;

    int b = blockIdx.y, chunk = blockIdx.x;
    int tid = threadIdx.x, w = tid >> 5, lane = tid & 31;

    for (int i = tid; i < KK * DD; i += 256) {
        s_qk[i] = g_qk[b * KK * DD + i];
        s_U[i] = 0.f;
    }
    if (tid < 12) s_Sp[tid] = 0.f;

    const __half* gbase = g_fh + ((size_t)b * NN + (size_t)chunk * ROWS_A) * DD;
    issue_batch(gbase, 0, smem, tid);

    unsigned long long acc2[KK][4];
#pragma unroll
    for (int k = 0; k < KK; k++)
#pragma unroll
        for (int j = 0; j < 4; j++) acc2[k][j] = 0ull;

    for (int nb = 0; nb < NBATCH; nb++) {
        asm volatile("cp.async.wait_group 0;\n" ::: "memory");
        __syncthreads();

        // ---- P1: partial dots.  thread = (part p, row) ----
        {
            int prow = tid & 63, p = tid >> 6;
            const uint4* fr = (const uint4*)(s_f + (nb & 1) * BATCH * DD + prow * DD);
            unsigned long long dot2[KK];
#pragma unroll
            for (int k = 0; k < KK; k++) dot2[k] = 0ull;
#pragma unroll
            for (int i = 0; i < 8; i++) {
                int ci = p * 8 + i;                       // global 8-col chunk
                uint4 fu = fr[ci ^ (prow & 7)];
                const __half2* hp = (const __half2*)&fu;
                unsigned long long f2[4];
#pragma unroll
                for (int j = 0; j < 4; j++) f2[j] = pkf2(__half22float2(hp[j]));
#pragma unroll
                for (int k = 0; k < KK; k++) {
                    const ulonglong2* qp =
                        (const ulonglong2*)(s_qk + k * DD + ci * 8);
                    ulonglong2 qa = qp[0], qb = qp[1];
                    fma2(dot2[k], f2[0], qa.x);
                    fma2(dot2[k], f2[1], qa.y);
                    fma2(dot2[k], f2[2], qb.x);
                    fma2(dot2[k], f2[3], qb.y);
                }
            }
#pragma unroll
            for (int k = 0; k < KK; k++) {
                float2 dv = upk2(dot2[k]);
                s_dot[p * KK * BATCH + k * BATCH + prow] = dv.x + dv.y;
            }
        }
        __syncthreads();

        if (nb + 1 < NBATCH) issue_batch(gbase, nb + 1, smem, tid);

        // ---- P2: per-row softmax (64 threads) + accS butterfly ----
        if (tid < 64) {
            int r = tid;
            float a[KK];
#pragma unroll
            for (int k = 0; k < KK; k++)
                a[k] = ((s_dot[0 * KK * BATCH + k * BATCH + r] +
                         s_dot[1 * KK * BATCH + k * BATCH + r]) +
                        (s_dot[2 * KK * BATCH + k * BATCH + r] +
                         s_dot[3 * KK * BATCH + k * BATCH + r]));
            float mx = a[0];
#pragma unroll
            for (int k = 1; k < KK; k++) mx = fmaxf(mx, a[k]);
            float se = 0.f;
#pragma unroll
            for (int k = 0; k < KK; k++) { a[k] = __expf(a[k] - mx); se += a[k]; }
            float inv = 1.f / se;
#pragma unroll
            for (int k = 0; k < KK; k++) {
                a[k] *= inv;
                s_a[r * KK + k] = a[k];
            }
            float s[KK];
#pragma unroll
            for (int k = 0; k < KK; k++) s[k] = a[k];
#pragma unroll
            for (int off = 16; off > 0; off >>= 1)
#pragma unroll
                for (int k = 0; k < KK; k++)
                    s[k] += __shfl_xor_sync(0xFFFFFFFFu, s[k], off);
            if (lane == 0)
#pragma unroll
                for (int k = 0; k < KK; k++) s_Sp[w * KK + k] += s[k];
        }
        __syncthreads();

        // ---- P3: tiled rank-K accumulate. warp w -> rows w*8..w*8+7,
        //          lane -> 8-col group ----
        {
            const uint4* fw = (const uint4*)(s_f + (nb & 1) * BATCH * DD);
#pragma unroll
            for (int rr = 0; rr < 8; rr++) {
                int r = w * 8 + rr;
                uint4 fu = fw[r * 32 + (lane ^ (r & 7))];
                const __half2* hp = (const __half2*)&fu;
                unsigned long long f2[4];
#pragma unroll
                for (int j = 0; j < 4; j++) f2[j] = pkf2(__half22float2(hp[j]));
                const float2* ap2 = (const float2*)(s_a + r * KK);
                float2 a01 = ap2[0], a23 = ap2[1], a45 = ap2[2];
                unsigned long long ap[KK] = {
                    pk2(a01.x, a01.x), pk2(a01.y, a01.y),
                    pk2(a23.x, a23.x), pk2(a23.y, a23.y),
                    pk2(a45.x, a45.x), pk2(a45.y, a45.y)};
#pragma unroll
                for (int k = 0; k < KK; k++)
#pragma unroll
                    for (int j = 0; j < 4; j++) fma2(acc2[k][j], ap[k], f2[j]);
            }
        }
        __syncthreads();
    }

    // ordered (deterministic) combine across the 8 warps
    for (int ww = 0; ww < 8; ww++) {
        if (w == ww) {
#pragma unroll
            for (int k = 0; k < KK; k++)
#pragma unroll
                for (int j = 0; j < 4; j++) {
                    float2 v = upk2(acc2[k][j]);
                    s_U[k * DD + lane * 8 + 2 * j]     += v.x;
                    s_U[k * DD + lane * 8 + 2 * j + 1] += v.y;
                }
        }
        __syncthreads();
    }

    float* pU = g_partU + (size_t)(b * CHUNKS + chunk) * KK * DD;
    for (int i = tid; i < KK * DD; i += 256) pU[i] = s_U[i];
    if (tid < KK)
        g_partS[(b * CHUNKS + chunk) * KK + tid] = s_Sp[tid] + s_Sp[KK + tid];
}

// ---------------------------------------------------------------------------
// Kernel C: per (b,k): reduce partials -> updates = Wv@U/(S+1e-8) ->
//           GRUCell -> LN -> MLP residual -> new slots.  block = 256.
// ---------------------------------------------------------------------------
__global__ void __launch_bounds__(256)
update_kernel(float* __restrict__ slots,
              const float* __restrict__ Wv,
              const float* __restrict__ Wih,
              const float* __restrict__ Whh,
              const float* __restrict__ bih,
              const float* __restrict__ bhh,
              const float* __restrict__ lnm_g,
              const float* __restrict__ lnm_b,
              const float* __restrict__ W1,
              const float* __restrict__ b1,
              const float* __restrict__ W2,
              const float* __restrict__ b2) {
    int k = blockIdx.x, b = blockIdx.y, t = threadIdx.x;
    __shared__ __align__(16) float U[DD];
    __shared__ __align__(16) float s_xv[HH];
    __shared__ __align__(16) float s_hp[HH];
    __shared__ float s_grz[2 * HH];
    __shared__ float s_gin[HH], s_ghn[HH];
    __shared__ float s_hn[HH];
    __shared__ __align__(16) float s_mm[HH];
    __shared__ __align__(16) float s_m1[2 * HH];
    __shared__ float s_st[4];

    {
        float u = 0.f;
#pragma unroll
        for (int c = 0; c < CHUNKS; c++)
            u += g_partU[((size_t)(b * CHUNKS + c) * KK + k) * DD + t];
        U[t] = u;
    }
    if (t < 32) {
        float S = (t < CHUNKS) ? g_partS[(b * CHUNKS + t) * KK + k] : 0.f;
#pragma unroll
        for (int off = 8; off > 0; off >>= 1)
            S += __shfl_xor_sync(0xFFFFFFFFu, S, off);
        if (t == 0) s_st[0] = 1.f / (S + 1e-8f);
    }
    if (t >= 64 && t < 128) s_hp[t - 64] = slots[(b * KK + k) * HH + (t - 64)];
    __syncthreads();

    {
        int o = t >> 2, q = t & 3;
        const float4* wv = (const float4*)(Wv + o * DD + q * 64);
        const float4* uu = (const float4*)(U + q * 64);
        float a0 = 0.f, a1 = 0.f;
#pragma unroll
        for (int i = 0; i < 16; i++) {
            float4 w4 = wv[i], u4 = uu[i];
            a0 += w4.x * u4.x + w4.z * u4.z;
            a1 += w4.y * u4.y + w4.w * u4.w;
        }
        float acc = a0 + a1;
        acc += __shfl_xor_sync(0xFFFFFFFFu, acc, 1);
        acc += __shfl_xor_sync(0xFFFFFFFFu, acc, 2);
        if (q == 0) s_xv[o] = acc * s_st[0];
    }
    __syncthreads();

    if (t < 192) {
        int gate = t >> 6, idx = t & 63;
        const float4* wi = (const float4*)(Wih + t * HH);
        const float4* wh = (const float4*)(Whh + t * HH);
        const float4* xv4 = (const float4*)s_xv;
        const float4* hp4 = (const float4*)s_hp;
        float gi = bih[t], gh = bhh[t];
#pragma unroll
        for (int i = 0; i < 16; i++) {
            float4 w4 = wi[i], x4 = xv4[i];
            gi += w4.x * x4.x + w4.y * x4.y + w4.z * x4.z + w4.w * x4.w;
            float4 v4 = wh[i], h4 = hp4[i];
            gh += v4.x * h4.x + v4.y * h4.y + v4.z * h4.z + v4.w * h4.w;
        }
        if (gate < 2) s_grz[t] = gi + gh;
        else { s_gin[idx] = gi; s_ghn[idx] = gh; }
    }
    __syncthreads();

    if (t < 64) {
        float r = 1.f / (1.f + __expf(-s_grz[t]));
        float z = 1.f / (1.f + __expf(-s_grz[64 + t]));
        float n = tanhf(s_gin[t] + r * s_ghn[t]);
        s_hn[t] = (1.f - z) * n + z * s_hp[t];
    }
    __syncthreads();
    if (t < 32) {
        float a = s_hn[t], c = s_hn[32 + t];
        float s1 = a + c, s2 = a * a + c * c;
#pragma unroll
        for (int off = 16; off > 0; off >>= 1) {
            s1 += __shfl_xor_sync(0xFFFFFFFFu, s1, off);
            s2 += __shfl_xor_sync(0xFFFFFFFFu, s2, off);
        }
        if (t == 0) {
            float mean = s1 * (1.f / HH);
            float var = s2 * (1.f / HH) - mean * mean;
            s_st[1] = mean;
            s_st[2] = rsqrtf(var + 1e-5f);
        }
    }
    __syncthreads();
    if (t < 64) s_mm[t] = (s_hn[t] - s_st[1]) * s_st[2] * lnm_g[t] + lnm_b[t];
    __syncthreads();

    {
        int o = t >> 1, hf = t & 1;
        const float4* w1 = (const float4*)(W1 + o * HH + hf * 32);
        const float4* mm4 = (const float4*)(s_mm + hf * 32);
        float acc = 0.f;
#pragma unroll
        for (int i = 0; i < 8; i++) {
            float4 w4 = w1[i], m4 = mm4[i];
            acc += w4.x * m4.x + w4.y * m4.y + w4.z * m4.z + w4.w * m4.w;
        }
        acc += __shfl_xor_sync(0xFFFFFFFFu, acc, 1);
        if (hf == 0) s_m1[o] = fmaxf(acc + b1[o], 0.f);
    }
    __syncthreads();

    {
        int o = t >> 2, q = t & 3;
        const float4* w2 = (const float4*)(W2 + o * 2 * HH + q * 32);
        const float4* m14 = (const float4*)(s_m1 + q * 32);
        float acc = 0.f;
#pragma unroll
        for (int i = 0; i < 8; i++) {
            float4 w4 = w2[i], m4 = m14[i];
            acc += w4.x * m4.x + w4.y * m4.y + w4.z * m4.z + w4.w * m4.w;
        }
        acc += __shfl_xor_sync(0xFFFFFFFFu, acc, 1);
        acc += __shfl_xor_sync(0xFFFFFFFFu, acc, 2);
        if (q == 0) slots[(b * KK + k) * HH + o] = s_hn[o] + acc + b2[o];
    }
}

// ---------------------------------------------------------------------------
extern "C" void kernel_launch(void* const* d_in, const int* in_sizes, int n_in,
                              void* d_out, int out_size) {
    const float* features   = (const float*)d_in[0];
    const float* slot_noise = (const float*)d_in[1];
    const float* slot_mu    = (const float*)d_in[2];
    const float* slot_sigma = (const float*)d_in[3];
    const float* ln_feat_g  = (const float*)d_in[4];
    const float* ln_feat_b  = (const float*)d_in[5];
    const float* ln_slot_g  = (const float*)d_in[6];
    const float* ln_slot_b  = (const float*)d_in[7];
    const float* ln_mlp_g   = (const float*)d_in[8];
    const float* ln_mlp_b   = (const float*)d_in[9];
    const float* Wk         = (const float*)d_in[10];
    const float* Wv         = (const float*)d_in[11];
    const float* Wq         = (const float*)d_in[12];
    const float* W_ih       = (const float*)d_in[13];
    const float* W_hh       = (const float*)d_in[14];
    const float* b_ih       = (const float*)d_in[15];
    const float* b_hh       = (const float*)d_in[16];
    const float* mlp_W1     = (const float*)d_in[17];
    const float* mlp_b1     = (const float*)d_in[18];
    const float* mlp_W2     = (const float*)d_in[19];
    const float* mlp_b2     = (const float*)d_in[20];

    float* slots = (float*)d_out;  // [B, K, H] lives in the output buffer

    static int smem_set = 0;
    if (!smem_set) {
        cudaFuncSetAttribute(attn_kernel,
                             cudaFuncAttributeMaxDynamicSharedMemorySize,
                             ATTN_SMEM);
        smem_set = 1;
    }

    init_slots_kernel<<<(BB * KK * HH + 255) / 256, 256>>>(slots, slot_noise,
                                                           slot_mu, slot_sigma);
    ln_feat_kernel<<<BB * NN / 8, 256>>>(features, ln_feat_g, ln_feat_b);

    dim3 gridSmall(KK, BB);
    dim3 gridA(CHUNKS, BB);
    for (int it = 0; it < 3; it++) {
        prep_kernel<<<gridSmall, 256>>>(slots, ln_slot_g, ln_slot_b, Wq, Wk);
        attn_kernel<<<gridA, 256, ATTN_SMEM>>>();
        update_kernel<<<gridSmall, 256>>>(slots, Wv, W_ih, W_hh, b_ih, b_hh,
                                          ln_mlp_g, ln_mlp_b, mlp_W1, mlp_b1,
                                          mlp_W2, mlp_b2);
    }
}

// round 4
// speedup vs baseline: 3.1120x; 1.3248x over previous
#include <cuda_runtime.h>
#include <cuda_fp16.h>

// Problem constants
#define BB 64
#define NN 4096
#define DD 256
#define KK 6
#define HH 64
#define CHUNKS 16
#define ROWS_A (NN / CHUNKS)     // 256 rows per block
#define BATCH 64
#define NBATCH (ROWS_A / BATCH)  // 4

// Device scratch (allocation-free rule: __device__ globals)
__device__ __half g_fh[(size_t)BB * NN * DD];     // LN(features) fp16 (128 MB)
__device__ __half g_qkh[BB * 16 * DD];            // qk fp16: rows 0-7 hi, 8-15 lo (swizzled)
__device__ float g_partU[BB * CHUNKS * KK * DD];  // per-chunk partial weighted sums
__device__ float g_partS[BB * CHUNKS * KK];       // per-chunk partial attention mass

// ---------------------------------------------------------------------------
// mma / ldmatrix helpers
// ---------------------------------------------------------------------------
__device__ __forceinline__ unsigned sptr(const void* p) {
    return (unsigned)__cvta_generic_to_shared(p);
}
__device__ __forceinline__ void ldsm4(unsigned& r0, unsigned& r1, unsigned& r2,
                                      unsigned& r3, unsigned addr) {
    asm volatile("ldmatrix.sync.aligned.m8n8.x4.shared.b16 {%0,%1,%2,%3}, [%4];"
                 : "=r"(r0), "=r"(r1), "=r"(r2), "=r"(r3) : "r"(addr));
}
__device__ __forceinline__ void ldsm4t(unsigned& r0, unsigned& r1, unsigned& r2,
                                       unsigned& r3, unsigned addr) {
    asm volatile("ldmatrix.sync.aligned.m8n8.x4.trans.shared.b16 {%0,%1,%2,%3}, [%4];"
                 : "=r"(r0), "=r"(r1), "=r"(r2), "=r"(r3) : "r"(addr));
}
__device__ __forceinline__ void ldsm2t(unsigned& r0, unsigned& r1, unsigned addr) {
    asm volatile("ldmatrix.sync.aligned.m8n8.x2.trans.shared.b16 {%0,%1}, [%2];"
                 : "=r"(r0), "=r"(r1) : "r"(addr));
}
__device__ __forceinline__ void mma16816(float* c, unsigned a0, unsigned a1,
                                         unsigned a2, unsigned a3,
                                         unsigned b0, unsigned b1) {
    asm volatile(
        "mma.sync.aligned.m16n8k16.row.col.f32.f16.f16.f32 "
        "{%0,%1,%2,%3}, {%4,%5,%6,%7}, {%8,%9}, {%0,%1,%2,%3};"
        : "+f"(c[0]), "+f"(c[1]), "+f"(c[2]), "+f"(c[3])
        : "r"(a0), "r"(a1), "r"(a2), "r"(a3), "r"(b0), "r"(b1));
}

// ---------------------------------------------------------------------------
// Kernel I: slots = mu + sigma * noise
// ---------------------------------------------------------------------------
__global__ void init_slots_kernel(float* __restrict__ slots,
                                  const float* __restrict__ noise,
                                  const float* __restrict__ mu,
                                  const float* __restrict__ sigma) {
    int i = blockIdx.x * blockDim.x + threadIdx.x;
    if (i < BB * KK * HH) {
        int h = i & (HH - 1);
        slots[i] = mu[h] + sigma[h] * noise[i];
    }
}

// ---------------------------------------------------------------------------
// Kernel Z: zero padding rows (6,7,14,15) of g_qkh, once per launch
// ---------------------------------------------------------------------------
__global__ void zero_qkh_kernel() {
    int b = blockIdx.x, t = threadIdx.x;
    g_qkh[b * 16 * DD + 6 * DD + t] = __ushort_as_half(0);
    g_qkh[b * 16 * DD + 7 * DD + t] = __ushort_as_half(0);
    g_qkh[b * 16 * DD + 14 * DD + t] = __ushort_as_half(0);
    g_qkh[b * 16 * DD + 15 * DD + t] = __ushort_as_half(0);
}

// ---------------------------------------------------------------------------
// Kernel LN: one-time LN(features) -> fp16. One warp per row of 256.
// ---------------------------------------------------------------------------
__global__ void __launch_bounds__(256)
ln_feat_kernel(const float* __restrict__ feat,
               const float* __restrict__ g,
               const float* __restrict__ bvec) {
    int row = blockIdx.x * 8 + (threadIdx.x >> 5);
    int lane = threadIdx.x & 31;
    const float* rp = feat + (size_t)row * DD + 8 * lane;
    float4 a = ((const float4*)rp)[0];
    float4 c = ((const float4*)rp)[1];
    float f[8] = {a.x, a.y, a.z, a.w, c.x, c.y, c.z, c.w};

    float s1 = 0.f, s2 = 0.f;
#pragma unroll
    for (int j = 0; j < 8; j++) { s1 += f[j]; s2 += f[j] * f[j]; }
#pragma unroll
    for (int off = 16; off > 0; off >>= 1) {
        s1 += __shfl_xor_sync(0xFFFFFFFFu, s1, off);
        s2 += __shfl_xor_sync(0xFFFFFFFFu, s2, off);
    }
    float mean = s1 * (1.f / DD);
    float var = s2 * (1.f / DD) - mean * mean;
    float rstd = rsqrtf(var + 1e-5f);

    float4 ga = ((const float4*)(g + 8 * lane))[0];
    float4 gc = ((const float4*)(g + 8 * lane))[1];
    float4 ba = ((const float4*)(bvec + 8 * lane))[0];
    float4 bc = ((const float4*)(bvec + 8 * lane))[1];
    float gg[8] = {ga.x, ga.y, ga.z, ga.w, gc.x, gc.y, gc.z, gc.w};
    float bb[8] = {ba.x, ba.y, ba.z, ba.w, bc.x, bc.y, bc.z, bc.w};
#pragma unroll
    for (int j = 0; j < 8; j++) f[j] = (f[j] - mean) * rstd * gg[j] + bb[j];

    __half2 h[4];
#pragma unroll
    for (int j = 0; j < 4; j++)
        h[j] = __float22half2_rn(make_float2(f[2 * j], f[2 * j + 1]));
    *(uint4*)(g_fh + (size_t)row * DD + 8 * lane) = *(uint4*)h;
}

// ---------------------------------------------------------------------------
// Kernel P: per (b,k): s = LN(slots); q = Wq@s; qk = 0.125*Wk^T@q -> fp16 hi/lo
// grid (KK, BB), block 256
// ---------------------------------------------------------------------------
__global__ void __launch_bounds__(256)
prep_kernel(const float* __restrict__ slots,
            const float* __restrict__ ln_g,
            const float* __restrict__ ln_b,
            const float* __restrict__ Wq,
            const float* __restrict__ Wk) {
    int k = blockIdx.x, b = blockIdx.y, t = threadIdx.x;
    __shared__ __align__(16) float s_s[HH];
    __shared__ __align__(16) float s_q[HH];
    __shared__ float s_st[2];

    if (t < HH) s_s[t] = slots[(b * KK + k) * HH + t];
    __syncthreads();

    if (t < 32) {
        float a = s_s[t], c = s_s[32 + t];
        float s1 = a + c, s2 = a * a + c * c;
#pragma unroll
        for (int off = 16; off > 0; off >>= 1) {
            s1 += __shfl_xor_sync(0xFFFFFFFFu, s1, off);
            s2 += __shfl_xor_sync(0xFFFFFFFFu, s2, off);
        }
        if (t == 0) {
            float mean = s1 * (1.f / HH);
            float var = s2 * (1.f / HH) - mean * mean;
            s_st[0] = mean;
            s_st[1] = rsqrtf(var + 1e-5f);
        }
    }
    __syncthreads();
    if (t < HH) s_s[t] = (s_s[t] - s_st[0]) * s_st[1] * ln_g[t] + ln_b[t];
    __syncthreads();

    {
        int o = t >> 2, q4 = t & 3;
        const float4* w = (const float4*)(Wq + o * HH + q4 * 16);
        const float4* sv = (const float4*)(s_s + q4 * 16);
        float acc = 0.f;
#pragma unroll
        for (int i = 0; i < 4; i++) {
            float4 w4 = w[i], s4 = sv[i];
            acc += w4.x * s4.x + w4.y * s4.y + w4.z * s4.z + w4.w * s4.w;
        }
        acc += __shfl_xor_sync(0xFFFFFFFFu, acc, 1);
        acc += __shfl_xor_sync(0xFFFFFFFFu, acc, 2);
        if (q4 == 0) s_q[o] = acc * 0.125f;
    }
    __syncthreads();

    {
        float a0 = 0.f, a1 = 0.f, a2 = 0.f, a3 = 0.f;
#pragma unroll
        for (int h = 0; h < HH; h += 4) {
            a0 += s_q[h]     * Wk[(h)     * DD + t];
            a1 += s_q[h + 1] * Wk[(h + 1) * DD + t];
            a2 += s_q[h + 2] * Wk[(h + 2) * DD + t];
            a3 += s_q[h + 3] * Wk[(h + 3) * DD + t];
        }
        float val = (a0 + a1) + (a2 + a3);
        __half hi = __float2half_rn(val);
        __half lo = __float2half_rn(val - __half2float(hi));
        // swizzled fp16 store: row r, 8-half chunk (t>>3) xor (r&7)
        int ch = t >> 3, wi = t & 7;
        int rh = k, rl = 8 + k;
        g_qkh[b * 16 * DD + rh * DD + (((ch ^ (rh & 7)) << 3) | wi)] = hi;
        g_qkh[b * 16 * DD + rl * DD + (((ch ^ (rl & 7)) << 3) | wi)] = lo;
    }
}

// ---------------------------------------------------------------------------
// Kernel A (hot): tensor-core attention streaming pass.
// grid (CHUNKS, BB), block 256 (8 warps). 256 rows/block, 4 batches of 64,
// double-buffered cp.async with 2-deep pipeline.
// smem: s_f 2x[64][256] f16 swizzled (64KB) | s_qk [16][256] f16 swizzled (8KB)
//       s_dot [2][64][8] f32 (4KB) | s_a [64][8] f16 (1KB) | s_Sp [12] f32
// ---------------------------------------------------------------------------
#define SMEM_F_BYTES (2 * BATCH * DD * 2)
#define SMEM_QK_OFF  SMEM_F_BYTES
#define SMEM_DOT_OFF (SMEM_QK_OFF + 16 * DD * 2)
#define SMEM_A_OFF   (SMEM_DOT_OFF + 2 * BATCH * 8 * 4)
#define SMEM_SP_OFF  (SMEM_A_OFF + BATCH * 8 * 2)
#define ATTN_SMEM    (SMEM_SP_OFF + 12 * 4)

__device__ __forceinline__ void issue_batch(const __half* gbase, int nb,
                                            char* smem, int tid) {
    const char* g = (const char*)(gbase + (size_t)nb * BATCH * DD);
    unsigned sbase = sptr(smem) + (nb & 1) * (BATCH * DD * 2);
#pragma unroll
    for (int it = 0; it < 8; it++) {
        int idx = tid + it * 256;
        int row = idx >> 5, j = idx & 31;
        unsigned dst = sbase + row * 512 + ((j ^ (row & 7)) << 4);
        const char* src = g + row * 512 + j * 16;
        asm volatile("cp.async.ca.shared.global [%0], [%1], 16;\n"
                     :: "r"(dst), "l"(src));
    }
    asm volatile("cp.async.commit_group;\n");
}

__global__ void __launch_bounds__(256, 2)
attn_kernel() {
    extern __shared__ __align__(16) char smem[];
    __half* s_qk = (__half*)(smem + SMEM_QK_OFF);
    float* s_dot = (float*)(smem + SMEM_DOT_OFF);
    __half* s_a  = (__half*)(smem + SMEM_A_OFF);
    float* s_Sp  = (float*)(smem + SMEM_SP_OFF);

    int b = blockIdx.y, chunk = blockIdx.x;
    int tid = threadIdx.x, w = tid >> 5, lane = tid & 31;

    // load swizzled qk (hi/lo) block: 512 uint4
    {
        const uint4* qs = (const uint4*)(g_qkh + b * 16 * DD);
        uint4* qd = (uint4*)s_qk;
        qd[tid] = qs[tid];
        qd[tid + 256] = qs[tid + 256];
    }

    const __half* gbase = g_fh + ((size_t)b * NN + (size_t)chunk * ROWS_A) * DD;
    issue_batch(gbase, 0, smem, tid);

    unsigned s_f_u  = sptr(smem);
    unsigned s_qk_u = sptr(s_qk);
    unsigned s_a_u  = sptr(s_a);

    float accS[KK];
#pragma unroll
    for (int k = 0; k < KK; k++) accS[k] = 0.f;
    float u0[4] = {0.f, 0.f, 0.f, 0.f};
    float u1[4] = {0.f, 0.f, 0.f, 0.f};

    int g4 = lane >> 2, t4 = lane & 3;

    for (int nb = 0; nb < NBATCH; nb++) {
        if (nb + 1 < NBATCH) {
            issue_batch(gbase, nb + 1, smem, tid);
            asm volatile("cp.async.wait_group 1;\n" ::: "memory");
        } else {
            asm volatile("cp.async.wait_group 0;\n" ::: "memory");
        }
        __syncthreads();

        unsigned fb = s_f_u + (nb & 1) * (BATCH * DD * 2);

        // ---- P1: dots via mma. warp = (row-tile rt, k-half kh) ----
        {
            int rt = w & 3, kh = w >> 2;
            int r0 = rt * 16;
            float c[4] = {0.f, 0.f, 0.f, 0.f};
            int arow = r0 + (lane & 15);
            int asel = lane >> 4;                    // 0/1 -> chunk +0/+1
            unsigned arow_base = fb + arow * 512;
            int brow = (lane & 7) + ((lane >> 4) << 3);  // 0-7 hi, 8-15 lo
            int bsel = (lane >> 3) & 1;
            unsigned brow_base = s_qk_u + brow * 512;
#pragma unroll
            for (int i = 0; i < 8; i++) {
                int kc = kh * 8 + i;
                unsigned a0, a1, a2, a3, bh0, bh1, bl0, bl1;
                int ach = 2 * kc + asel;
                ldsm4(a0, a1, a2, a3,
                      arow_base + ((ach ^ (arow & 7)) << 4));
                int bch = 2 * kc + bsel;
                ldsm4(bh0, bh1, bl0, bl1,
                      brow_base + ((bch ^ (brow & 7)) << 4));
                mma16816(c, a0, a1, a2, a3, bh0, bh1);
                mma16816(c, a0, a1, a2, a3, bl0, bl1);
            }
            // store D -> s_dot[kh][row][col]
            float* dbase = s_dot + kh * (BATCH * 8);
            *(float2*)(dbase + (r0 + g4) * 8 + 2 * t4)     = make_float2(c[0], c[1]);
            *(float2*)(dbase + (r0 + g4 + 8) * 8 + 2 * t4) = make_float2(c[2], c[3]);
        }
        __syncthreads();

        // ---- P2: per-row softmax (threads 0-63), a -> fp16 ----
        if (tid < 64) {
            int r = tid;
            float4 da = ((const float4*)(s_dot + r * 8))[0];
            float4 db = ((const float4*)(s_dot + r * 8))[1];
            float4 ea = ((const float4*)(s_dot + BATCH * 8 + r * 8))[0];
            float4 eb = ((const float4*)(s_dot + BATCH * 8 + r * 8))[1];
            float d[KK] = {da.x + ea.x, da.y + ea.y, da.z + ea.z,
                           da.w + ea.w, db.x + eb.x, db.y + eb.y};
            float mx = d[0];
#pragma unroll
            for (int k = 1; k < KK; k++) mx = fmaxf(mx, d[k]);
            float se = 0.f;
#pragma unroll
            for (int k = 0; k < KK; k++) { d[k] = __expf(d[k] - mx); se += d[k]; }
            float inv = 1.f / se;
            __half h[KK];
#pragma unroll
            for (int k = 0; k < KK; k++) {
                h[k] = __float2half_rn(d[k] * inv);
                accS[k] += __half2float(h[k]);
            }
            unsigned p0 = ((unsigned)__half_as_ushort(h[1]) << 16) | __half_as_ushort(h[0]);
            unsigned p1 = ((unsigned)__half_as_ushort(h[3]) << 16) | __half_as_ushort(h[2]);
            unsigned p2 = ((unsigned)__half_as_ushort(h[5]) << 16) | __half_as_ushort(h[4]);
            uint4 pv = make_uint4(p0, p1, p2, 0u);
            *(uint4*)(s_a + r * 8) = pv;
        }
        __syncthreads();

        // ---- P3: U += F^T a via mma.trans. warp w -> col-tiles {w, w+8} ----
        {
            int trow = (lane & 7) + ((lane >> 4) << 3);
            int tsel = (lane >> 3) & 1;
#pragma unroll
            for (int kc = 0; kc < 4; kc++) {
                unsigned b0, b1;
                ldsm2t(b0, b1, s_a_u + (kc * 16 + (lane & 15)) * 16);
                int row = kc * 16 + trow;
                unsigned rbase = fb + row * 512;
                {
                    unsigned a0, a1, a2, a3;
                    int ch = w * 2 + tsel;
                    ldsm4t(a0, a1, a2, a3, rbase + ((ch ^ (row & 7)) << 4));
                    mma16816(u0, a0, a1, a2, a3, b0, b1);
                }
                {
                    unsigned a0, a1, a2, a3;
                    int ch = (w + 8) * 2 + tsel;
                    ldsm4t(a0, a1, a2, a3, rbase + ((ch ^ (row & 7)) << 4));
                    mma16816(u1, a0, a1, a2, a3, b0, b1);
                }
            }
        }
        __syncthreads();
    }

    // ---- epilogue: write U tiles and S ----
    {
        float* base = g_partU + (size_t)(b * CHUNKS + chunk) * KK * DD;
        if (t4 < 3) {
            int d0 = w * 16;
            base[(2 * t4) * DD + d0 + g4]         = u0[0];
            base[(2 * t4 + 1) * DD + d0 + g4]     = u0[1];
            base[(2 * t4) * DD + d0 + 8 + g4]     = u0[2];
            base[(2 * t4 + 1) * DD + d0 + 8 + g4] = u0[3];
            int d1 = (w + 8) * 16;
            base[(2 * t4) * DD + d1 + g4]         = u1[0];
            base[(2 * t4 + 1) * DD + d1 + g4]     = u1[1];
            base[(2 * t4) * DD + d1 + 8 + g4]     = u1[2];
            base[(2 * t4 + 1) * DD + d1 + 8 + g4] = u1[3];
        }
    }
    if (tid < 64) {
#pragma unroll
        for (int off = 16; off > 0; off >>= 1)
#pragma unroll
            for (int k = 0; k < KK; k++)
                accS[k] += __shfl_xor_sync(0xFFFFFFFFu, accS[k], off);
        if (lane == 0)
#pragma unroll
            for (int k = 0; k < KK; k++) s_Sp[w * KK + k] = accS[k];
    }
    __syncthreads();
    if (tid < KK)
        g_partS[(b * CHUNKS + chunk) * KK + tid] = s_Sp[tid] + s_Sp[KK + tid];
}

// ---------------------------------------------------------------------------
// Kernel C: per (b,k): reduce partials -> updates = Wv@U/(S+1e-8) ->
//           GRUCell -> LN -> MLP residual -> new slots.  block = 256.
// ---------------------------------------------------------------------------
__global__ void __launch_bounds__(256)
update_kernel(float* __restrict__ slots,
              const float* __restrict__ Wv,
              const float* __restrict__ Wih,
              const float* __restrict__ Whh,
              const float* __restrict__ bih,
              const float* __restrict__ bhh,
              const float* __restrict__ lnm_g,
              const float* __restrict__ lnm_b,
              const float* __restrict__ W1,
              const float* __restrict__ b1,
              const float* __restrict__ W2,
              const float* __restrict__ b2) {
    int k = blockIdx.x, b = blockIdx.y, t = threadIdx.x;
    __shared__ __align__(16) float U[DD];
    __shared__ __align__(16) float s_xv[HH];
    __shared__ __align__(16) float s_hp[HH];
    __shared__ float s_grz[2 * HH];
    __shared__ float s_gin[HH], s_ghn[HH];
    __shared__ float s_hn[HH];
    __shared__ __align__(16) float s_mm[HH];
    __shared__ __align__(16) float s_m1[2 * HH];
    __shared__ float s_st[4];

    {
        float u = 0.f;
#pragma unroll
        for (int c = 0; c < CHUNKS; c++)
            u += g_partU[((size_t)(b * CHUNKS + c) * KK + k) * DD + t];
        U[t] = u;
    }
    if (t < 32) {
        float S = (t < CHUNKS) ? g_partS[(b * CHUNKS + t) * KK + k] : 0.f;
#pragma unroll
        for (int off = 8; off > 0; off >>= 1)
            S += __shfl_xor_sync(0xFFFFFFFFu, S, off);
        if (t == 0) s_st[0] = 1.f / (S + 1e-8f);
    }
    if (t >= 64 && t < 128) s_hp[t - 64] = slots[(b * KK + k) * HH + (t - 64)];
    __syncthreads();

    {
        int o = t >> 2, q = t & 3;
        const float4* wv = (const float4*)(Wv + o * DD + q * 64);
        const float4* uu = (const float4*)(U + q * 64);
        float a0 = 0.f, a1 = 0.f;
#pragma unroll
        for (int i = 0; i < 16; i++) {
            float4 w4 = wv[i], u4 = uu[i];
            a0 += w4.x * u4.x + w4.z * u4.z;
            a1 += w4.y * u4.y + w4.w * u4.w;
        }
        float acc = a0 + a1;
        acc += __shfl_xor_sync(0xFFFFFFFFu, acc, 1);
        acc += __shfl_xor_sync(0xFFFFFFFFu, acc, 2);
        if (q == 0) s_xv[o] = acc * s_st[0];
    }
    __syncthreads();

    if (t < 192) {
        int gate = t >> 6, idx = t & 63;
        const float4* wi = (const float4*)(Wih + t * HH);
        const float4* wh = (const float4*)(Whh + t * HH);
        const float4* xv4 = (const float4*)s_xv;
        const float4* hp4 = (const float4*)s_hp;
        float gi = bih[t], gh = bhh[t];
#pragma unroll
        for (int i = 0; i < 16; i++) {
            float4 w4 = wi[i], x4 = xv4[i];
            gi += w4.x * x4.x + w4.y * x4.y + w4.z * x4.z + w4.w * x4.w;
            float4 v4 = wh[i], h4 = hp4[i];
            gh += v4.x * h4.x + v4.y * h4.y + v4.z * h4.z + v4.w * h4.w;
        }
        if (gate < 2) s_grz[t] = gi + gh;
        else { s_gin[idx] = gi; s_ghn[idx] = gh; }
    }
    __syncthreads();

    if (t < 64) {
        float r = 1.f / (1.f + __expf(-s_grz[t]));
        float z = 1.f / (1.f + __expf(-s_grz[64 + t]));
        float n = tanhf(s_gin[t] + r * s_ghn[t]);
        s_hn[t] = (1.f - z) * n + z * s_hp[t];
    }
    __syncthreads();
    if (t < 32) {
        float a = s_hn[t], c = s_hn[32 + t];
        float s1 = a + c, s2 = a * a + c * c;
#pragma unroll
        for (int off = 16; off > 0; off >>= 1) {
            s1 += __shfl_xor_sync(0xFFFFFFFFu, s1, off);
            s2 += __shfl_xor_sync(0xFFFFFFFFu, s2, off);
        }
        if (t == 0) {
            float mean = s1 * (1.f / HH);
            float var = s2 * (1.f / HH) - mean * mean;
            s_st[1] = mean;
            s_st[2] = rsqrtf(var + 1e-5f);
        }
    }
    __syncthreads();
    if (t < 64) s_mm[t] = (s_hn[t] - s_st[1]) * s_st[2] * lnm_g[t] + lnm_b[t];
    __syncthreads();

    {
        int o = t >> 1, hf = t & 1;
        const float4* w1 = (const float4*)(W1 + o * HH + hf * 32);
        const float4* mm4 = (const float4*)(s_mm + hf * 32);
        float acc = 0.f;
#pragma unroll
        for (int i = 0; i < 8; i++) {
            float4 w4 = w1[i], m4 = mm4[i];
            acc += w4.x * m4.x + w4.y * m4.y + w4.z * m4.z + w4.w * m4.w;
        }
        acc += __shfl_xor_sync(0xFFFFFFFFu, acc, 1);
        if (hf == 0) s_m1[o] = fmaxf(acc + b1[o], 0.f);
    }
    __syncthreads();

    {
        int o = t >> 2, q = t & 3;
        const float4* w2 = (const float4*)(W2 + o * 2 * HH + q * 32);
        const float4* m14 = (const float4*)(s_m1 + q * 32);
        float acc = 0.f;
#pragma unroll
        for (int i = 0; i < 8; i++) {
            float4 w4 = w2[i], m4 = m14[i];
            acc += w4.x * m4.x + w4.y * m4.y + w4.z * m4.z + w4.w * m4.w;
        }
        acc += __shfl_xor_sync(0xFFFFFFFFu, acc, 1);
        acc += __shfl_xor_sync(0xFFFFFFFFu, acc, 2);
        if (q == 0) slots[(b * KK + k) * HH + o] = s_hn[o] + acc + b2[o];
    }
}

// ---------------------------------------------------------------------------
extern "C" void kernel_launch(void* const* d_in, const int* in_sizes, int n_in,
                              void* d_out, int out_size) {
    const float* features   = (const float*)d_in[0];
    const float* slot_noise = (const float*)d_in[1];
    const float* slot_mu    = (const float*)d_in[2];
    const float* slot_sigma = (const float*)d_in[3];
    const float* ln_feat_g  = (const float*)d_in[4];
    const float* ln_feat_b  = (const float*)d_in[5];
    const float* ln_slot_g  = (const float*)d_in[6];
    const float* ln_slot_b  = (const float*)d_in[7];
    const float* ln_mlp_g   = (const float*)d_in[8];
    const float* ln_mlp_b   = (const float*)d_in[9];
    const float* Wk         = (const float*)d_in[10];
    const float* Wv         = (const float*)d_in[11];
    const float* Wq         = (const float*)d_in[12];
    const float* W_ih       = (const float*)d_in[13];
    const float* W_hh       = (const float*)d_in[14];
    const float* b_ih       = (const float*)d_in[15];
    const float* b_hh       = (const float*)d_in[16];
    const float* mlp_W1     = (const float*)d_in[17];
    const float* mlp_b1     = (const float*)d_in[18];
    const float* mlp_W2     = (const float*)d_in[19];
    const float* mlp_b2     = (const float*)d_in[20];

    float* slots = (float*)d_out;  // [B, K, H] lives in the output buffer

    static int smem_set = 0;
    if (!smem_set) {
        cudaFuncSetAttribute(attn_kernel,
                             cudaFuncAttributeMaxDynamicSharedMemorySize,
                             ATTN_SMEM);
        smem_set = 1;
    }

    init_slots_kernel<<<(BB * KK * HH + 255) / 256, 256>>>(slots, slot_noise,
                                                           slot_mu, slot_sigma);
    zero_qkh_kernel<<<BB, 256>>>();
    ln_feat_kernel<<<BB * NN / 8, 256>>>(features, ln_feat_g, ln_feat_b);

    dim3 gridSmall(KK, BB);
    dim3 gridA(CHUNKS, BB);
    for (int it = 0; it < 3; it++) {
        prep_kernel<<<gridSmall, 256>>>(slots, ln_slot_g, ln_slot_b, Wq, Wk);
        attn_kernel<<<gridA, 256, ATTN_SMEM>>>();
        update_kernel<<<gridSmall, 256>>>(slots, Wv, W_ih, W_hh, b_ih, b_hh,
                                          ln_mlp_g, ln_mlp_b, mlp_W1, mlp_b1,
                                          mlp_W2, mlp_b2);
    }
}

// round 5
// speedup vs baseline: 3.1588x; 1.0150x over previous
#include <cuda_runtime.h>
#include <cuda_fp16.h>

// Problem constants
#define BB 64
#define NN 4096
#define DD 256
#define KK 6
#define HH 64
#define CHUNKS 32
#define ROWS_A (NN / CHUNKS)     // 128 rows per block
#define BATCH 64
#define NBATCH (ROWS_A / BATCH)  // 2

// Device scratch (allocation-free rule: __device__ globals)
__device__ __half g_fh[(size_t)BB * NN * DD];     // LN(features) fp16 (128 MB)
__device__ __half g_qkh[BB * 16 * DD];            // qk fp16: rows 0-7 hi, 8-15 lo (swizzled)
__device__ float g_partU[BB * CHUNKS * KK * DD];  // per-chunk partial weighted sums
__device__ float g_partS[BB * CHUNKS * KK];       // per-chunk partial attention mass

// ---------------------------------------------------------------------------
// mma / ldmatrix helpers
// ---------------------------------------------------------------------------
__device__ __forceinline__ unsigned sptr(const void* p) {
    return (unsigned)__cvta_generic_to_shared(p);
}
__device__ __forceinline__ void ldsm4(unsigned& r0, unsigned& r1, unsigned& r2,
                                      unsigned& r3, unsigned addr) {
    asm volatile("ldmatrix.sync.aligned.m8n8.x4.shared.b16 {%0,%1,%2,%3}, [%4];"
                 : "=r"(r0), "=r"(r1), "=r"(r2), "=r"(r3) : "r"(addr));
}
__device__ __forceinline__ void ldsm4t(unsigned& r0, unsigned& r1, unsigned& r2,
                                       unsigned& r3, unsigned addr) {
    asm volatile("ldmatrix.sync.aligned.m8n8.x4.trans.shared.b16 {%0,%1,%2,%3}, [%4];"
                 : "=r"(r0), "=r"(r1), "=r"(r2), "=r"(r3) : "r"(addr));
}
__device__ __forceinline__ void ldsm2t(unsigned& r0, unsigned& r1, unsigned addr) {
    asm volatile("ldmatrix.sync.aligned.m8n8.x2.trans.shared.b16 {%0,%1}, [%2];"
                 : "=r"(r0), "=r"(r1) : "r"(addr));
}
__device__ __forceinline__ void mma16816(float* c, unsigned a0, unsigned a1,
                                         unsigned a2, unsigned a3,
                                         unsigned b0, unsigned b1) {
    asm volatile(
        "mma.sync.aligned.m16n8k16.row.col.f32.f16.f16.f32 "
        "{%0,%1,%2,%3}, {%4,%5,%6,%7}, {%8,%9}, {%0,%1,%2,%3};"
        : "+f"(c[0]), "+f"(c[1]), "+f"(c[2]), "+f"(c[3])
        : "r"(a0), "r"(a1), "r"(a2), "r"(a3), "r"(b0), "r"(b1));
}

// ---------------------------------------------------------------------------
// Shared prep phase: s_s[0..63] holds the slot vector (synced).
// Computes LN -> q = Wq@s*0.125 -> qk = Wk^T q -> fp16 hi/lo swizzled store.
// All 256 threads participate.
// ---------------------------------------------------------------------------
__device__ __forceinline__ void prep_phase(int b, int k, int t,
                                           float* s_s, float* s_q, float* s_st,
                                           const float* __restrict__ ln_g,
                                           const float* __restrict__ ln_b,
                                           const float* __restrict__ Wq,
                                           const float* __restrict__ Wk) {
    if (t < 32) {
        float a = s_s[t], c = s_s[32 + t];
        float s1 = a + c, s2 = a * a + c * c;
#pragma unroll
        for (int off = 16; off > 0; off >>= 1) {
            s1 += __shfl_xor_sync(0xFFFFFFFFu, s1, off);
            s2 += __shfl_xor_sync(0xFFFFFFFFu, s2, off);
        }
        if (t == 0) {
            float mean = s1 * (1.f / HH);
            float var = s2 * (1.f / HH) - mean * mean;
            s_st[0] = mean;
            s_st[1] = rsqrtf(var + 1e-5f);
        }
    }
    __syncthreads();
    if (t < HH) s_s[t] = (s_s[t] - s_st[0]) * s_st[1] * ln_g[t] + ln_b[t];
    __syncthreads();

    {
        int o = t >> 2, q4 = t & 3;
        const float4* w = (const float4*)(Wq + o * HH + q4 * 16);
        const float4* sv = (const float4*)(s_s + q4 * 16);
        float acc = 0.f;
#pragma unroll
        for (int i = 0; i < 4; i++) {
            float4 w4 = w[i], s4 = sv[i];
            acc += w4.x * s4.x + w4.y * s4.y + w4.z * s4.z + w4.w * s4.w;
        }
        acc += __shfl_xor_sync(0xFFFFFFFFu, acc, 1);
        acc += __shfl_xor_sync(0xFFFFFFFFu, acc, 2);
        if (q4 == 0) s_q[o] = acc * 0.125f;
    }
    __syncthreads();

    {
        float a0 = 0.f, a1 = 0.f, a2 = 0.f, a3 = 0.f;
#pragma unroll
        for (int h = 0; h < HH; h += 4) {
            a0 += s_q[h]     * Wk[(h)     * DD + t];
            a1 += s_q[h + 1] * Wk[(h + 1) * DD + t];
            a2 += s_q[h + 2] * Wk[(h + 2) * DD + t];
            a3 += s_q[h + 3] * Wk[(h + 3) * DD + t];
        }
        float val = (a0 + a1) + (a2 + a3);
        __half hi = __float2half_rn(val);
        __half lo = __float2half_rn(val - __half2float(hi));
        int ch = t >> 3, wi = t & 7;
        int rh = k, rl = 8 + k;
        g_qkh[b * 16 * DD + rh * DD + (((ch ^ (rh & 7)) << 3) | wi)] = hi;
        g_qkh[b * 16 * DD + rl * DD + (((ch ^ (rl & 7)) << 3) | wi)] = lo;
    }
}

// ---------------------------------------------------------------------------
// Kernel IP: fused slot init + qk padding zero + first prep. grid (KK, BB).
// ---------------------------------------------------------------------------
__global__ void __launch_bounds__(256)
init_prep_kernel(float* __restrict__ slots,
                 const float* __restrict__ noise,
                 const float* __restrict__ mu,
                 const float* __restrict__ sigma,
                 const float* __restrict__ ln_g,
                 const float* __restrict__ ln_b,
                 const float* __restrict__ Wq,
                 const float* __restrict__ Wk) {
    int k = blockIdx.x, b = blockIdx.y, t = threadIdx.x;
    __shared__ __align__(16) float s_s[HH];
    __shared__ __align__(16) float s_q[HH];
    __shared__ float s_st[2];

    if (k == 0) {  // zero qkh padding rows 6,7,14,15 for this b
        __half z = __ushort_as_half(0);
        g_qkh[b * 16 * DD + 6 * DD + t] = z;
        g_qkh[b * 16 * DD + 7 * DD + t] = z;
        g_qkh[b * 16 * DD + 14 * DD + t] = z;
        g_qkh[b * 16 * DD + 15 * DD + t] = z;
    }
    if (t < HH) {
        float sv = mu[t] + sigma[t] * noise[(b * KK + k) * HH + t];
        slots[(b * KK + k) * HH + t] = sv;
        s_s[t] = sv;
    }
    __syncthreads();
    prep_phase(b, k, t, s_s, s_q, s_st, ln_g, ln_b, Wq, Wk);
}

// ---------------------------------------------------------------------------
// Kernel LN: one-time LN(features) -> fp16. 2 rows per warp for MLP.
// grid = B*N/16 blocks of 256 threads.
// ---------------------------------------------------------------------------
__global__ void __launch_bounds__(256)
ln_feat_kernel(const float* __restrict__ feat,
               const float* __restrict__ g,
               const float* __restrict__ bvec) {
    size_t r0 = (size_t)blockIdx.x * 16 + (threadIdx.x >> 5) * 2;
    int lane = threadIdx.x & 31;
    const float* p0 = feat + r0 * DD + 8 * lane;
    float4 a0 = ((const float4*)p0)[0];
    float4 c0 = ((const float4*)p0)[1];
    float4 a1 = ((const float4*)(p0 + DD))[0];
    float4 c1 = ((const float4*)(p0 + DD))[1];
    float f0[8] = {a0.x, a0.y, a0.z, a0.w, c0.x, c0.y, c0.z, c0.w};
    float f1[8] = {a1.x, a1.y, a1.z, a1.w, c1.x, c1.y, c1.z, c1.w};

    float s10 = 0.f, s20 = 0.f, s11 = 0.f, s21 = 0.f;
#pragma unroll
    for (int j = 0; j < 8; j++) {
        s10 += f0[j]; s20 += f0[j] * f0[j];
        s11 += f1[j]; s21 += f1[j] * f1[j];
    }
#pragma unroll
    for (int off = 16; off > 0; off >>= 1) {
        s10 += __shfl_xor_sync(0xFFFFFFFFu, s10, off);
        s20 += __shfl_xor_sync(0xFFFFFFFFu, s20, off);
        s11 += __shfl_xor_sync(0xFFFFFFFFu, s11, off);
        s21 += __shfl_xor_sync(0xFFFFFFFFu, s21, off);
    }
    float m0 = s10 * (1.f / DD), m1 = s11 * (1.f / DD);
    float r0s = rsqrtf(s20 * (1.f / DD) - m0 * m0 + 1e-5f);
    float r1s = rsqrtf(s21 * (1.f / DD) - m1 * m1 + 1e-5f);

    float4 ga = ((const float4*)(g + 8 * lane))[0];
    float4 gc = ((const float4*)(g + 8 * lane))[1];
    float4 ba = ((const float4*)(bvec + 8 * lane))[0];
    float4 bc = ((const float4*)(bvec + 8 * lane))[1];
    float gg[8] = {ga.x, ga.y, ga.z, ga.w, gc.x, gc.y, gc.z, gc.w};
    float bb[8] = {ba.x, ba.y, ba.z, ba.w, bc.x, bc.y, bc.z, bc.w};

    __half2 h0[4], h1[4];
#pragma unroll
    for (int j = 0; j < 4; j++) {
        float x0 = (f0[2 * j] - m0) * r0s * gg[2 * j] + bb[2 * j];
        float y0 = (f0[2 * j + 1] - m0) * r0s * gg[2 * j + 1] + bb[2 * j + 1];
        float x1 = (f1[2 * j] - m1) * r1s * gg[2 * j] + bb[2 * j];
        float y1 = (f1[2 * j + 1] - m1) * r1s * gg[2 * j + 1] + bb[2 * j + 1];
        h0[j] = __float22half2_rn(make_float2(x0, y0));
        h1[j] = __float22half2_rn(make_float2(x1, y1));
    }
    *(uint4*)(g_fh + r0 * DD + 8 * lane) = *(uint4*)h0;
    *(uint4*)(g_fh + (r0 + 1) * DD + 8 * lane) = *(uint4*)h1;
}

// ---------------------------------------------------------------------------
// Kernel A (hot): tensor-core attention streaming pass.
// grid (CHUNKS, BB) = 2048 blocks, 256 threads. 128 rows/block in 2 batches;
// both batches cp.async'd upfront; P1(nb) overlapped with P3(nb-1).
// ---------------------------------------------------------------------------
#define SMEM_F_BYTES (2 * BATCH * DD * 2)
#define SMEM_QK_OFF  SMEM_F_BYTES
#define SMEM_DOT_OFF (SMEM_QK_OFF + 16 * DD * 2)
#define SMEM_A_OFF   (SMEM_DOT_OFF + 2 * BATCH * 8 * 4)
#define SMEM_SP_OFF  (SMEM_A_OFF + 2 * BATCH * 8 * 2)
#define ATTN_SMEM    (SMEM_SP_OFF + 12 * 4)

__device__ __forceinline__ void issue_batch(const __half* gbase, int nb,
                                            char* smem, int tid) {
    const char* g = (const char*)(gbase + (size_t)nb * BATCH * DD);
    unsigned sbase = sptr(smem) + (nb & 1) * (BATCH * DD * 2);
#pragma unroll
    for (int it = 0; it < 8; it++) {
        int idx = tid + it * 256;
        int row = idx >> 5, j = idx & 31;
        unsigned dst = sbase + row * 512 + ((j ^ (row & 7)) << 4);
        const char* src = g + row * 512 + j * 16;
        asm volatile("cp.async.ca.shared.global [%0], [%1], 16;\n"
                     :: "r"(dst), "l"(src));
    }
    asm volatile("cp.async.commit_group;\n");
}

__global__ void __launch_bounds__(256, 2)
attn_kernel() {
    extern __shared__ __align__(16) char smem[];
    __half* s_qk = (__half*)(smem + SMEM_QK_OFF);
    float* s_dot = (float*)(smem + SMEM_DOT_OFF);
    __half* s_a  = (__half*)(smem + SMEM_A_OFF);
    float* s_Sp  = (float*)(smem + SMEM_SP_OFF);

    int b = blockIdx.y, chunk = blockIdx.x;
    int tid = threadIdx.x, w = tid >> 5, lane = tid & 31;

    // load swizzled qk (hi/lo) block: 512 uint4
    {
        const uint4* qs = (const uint4*)(g_qkh + b * 16 * DD);
        uint4* qd = (uint4*)s_qk;
        qd[tid] = qs[tid];
        qd[tid + 256] = qs[tid + 256];
    }

    const __half* gbase = g_fh + ((size_t)b * NN + (size_t)chunk * ROWS_A) * DD;
    issue_batch(gbase, 0, smem, tid);
    issue_batch(gbase, 1, smem, tid);

    unsigned s_f_u  = sptr(smem);
    unsigned s_qk_u = sptr(s_qk);
    unsigned s_a_u  = sptr(s_a);

    float accS[KK];
#pragma unroll
    for (int k = 0; k < KK; k++) accS[k] = 0.f;
    float u0[4] = {0.f, 0.f, 0.f, 0.f};
    float u1[4] = {0.f, 0.f, 0.f, 0.f};

    int g4 = lane >> 2, t4 = lane & 3;

    // P1 fragment index precompute
    int rt = w & 3, kh = w >> 2;
    int r0 = rt * 16;
    int arow = r0 + (lane & 15);
    int asel = lane >> 4;
    int brow = (lane & 7) + ((lane >> 4) << 3);
    int bsel = (lane >> 3) & 1;
    unsigned brow_base = s_qk_u + brow * 512;
    // P3 fragment index precompute
    int trow = (lane & 7) + ((lane >> 4) << 3);
    int tsel = (lane >> 3) & 1;

#pragma unroll
    for (int nb = 0; nb < NBATCH; nb++) {
        if (nb == 0) {
            asm volatile("cp.async.wait_group 1;\n" ::: "memory");
        } else {
            asm volatile("cp.async.wait_group 0;\n" ::: "memory");
        }
        __syncthreads();

        unsigned fb = s_f_u + (nb & 1) * (BATCH * DD * 2);

        // ---- P1: dots via mma on batch nb ----
        {
            float c[4] = {0.f, 0.f, 0.f, 0.f};
            unsigned arow_base = fb + arow * 512;
#pragma unroll
            for (int i = 0; i < 8; i++) {
                int kc = kh * 8 + i;
                unsigned a0, a1, a2, a3, bh0, bh1, bl0, bl1;
                int ach = 2 * kc + asel;
                ldsm4(a0, a1, a2, a3, arow_base + ((ach ^ (arow & 7)) << 4));
                int bch = 2 * kc + bsel;
                ldsm4(bh0, bh1, bl0, bl1, brow_base + ((bch ^ (brow & 7)) << 4));
                mma16816(c, a0, a1, a2, a3, bh0, bh1);
                mma16816(c, a0, a1, a2, a3, bl0, bl1);
            }
            float* dbase = s_dot + kh * (BATCH * 8);
            *(float2*)(dbase + (r0 + g4) * 8 + 2 * t4)     = make_float2(c[0], c[1]);
            *(float2*)(dbase + (r0 + g4 + 8) * 8 + 2 * t4) = make_float2(c[2], c[3]);
        }

        // ---- P3 for previous batch (no barrier needed: disjoint smem) ----
        if (nb > 0) {
            unsigned fp = s_f_u + ((nb - 1) & 1) * (BATCH * DD * 2);
            unsigned ap = s_a_u + ((nb - 1) & 1) * (BATCH * 8 * 2);
#pragma unroll
            for (int kc = 0; kc < 4; kc++) {
                unsigned b0, b1;
                ldsm2t(b0, b1, ap + (kc * 16 + (lane & 15)) * 16);
                int row = kc * 16 + trow;
                unsigned rbase = fp + row * 512;
                {
                    unsigned a0, a1, a2, a3;
                    int ch = w * 2 + tsel;
                    ldsm4t(a0, a1, a2, a3, rbase + ((ch ^ (row & 7)) << 4));
                    mma16816(u0, a0, a1, a2, a3, b0, b1);
                }
                {
                    unsigned a0, a1, a2, a3;
                    int ch = (w + 8) * 2 + tsel;
                    ldsm4t(a0, a1, a2, a3, rbase + ((ch ^ (row & 7)) << 4));
                    mma16816(u1, a0, a1, a2, a3, b0, b1);
                }
            }
        }
        __syncthreads();

        // ---- P2: per-row softmax (threads 0-63), a -> fp16 ----
        if (tid < 64) {
            int r = tid;
            float4 da = ((const float4*)(s_dot + r * 8))[0];
            float4 db = ((const float4*)(s_dot + r * 8))[1];
            float4 ea = ((const float4*)(s_dot + BATCH * 8 + r * 8))[0];
            float4 eb = ((const float4*)(s_dot + BATCH * 8 + r * 8))[1];
            float d[KK] = {da.x + ea.x, da.y + ea.y, da.z + ea.z,
                           da.w + ea.w, db.x + eb.x, db.y + eb.y};
            float mx = d[0];
#pragma unroll
            for (int k = 1; k < KK; k++) mx = fmaxf(mx, d[k]);
            float se = 0.f;
#pragma unroll
            for (int k = 0; k < KK; k++) { d[k] = __expf(d[k] - mx); se += d[k]; }
            float inv = 1.f / se;
            __half h[KK];
#pragma unroll
            for (int k = 0; k < KK; k++) {
                h[k] = __float2half_rn(d[k] * inv);
                accS[k] += __half2float(h[k]);
            }
            unsigned p0 = ((unsigned)__half_as_ushort(h[1]) << 16) | __half_as_ushort(h[0]);
            unsigned p1 = ((unsigned)__half_as_ushort(h[3]) << 16) | __half_as_ushort(h[2]);
            unsigned p2 = ((unsigned)__half_as_ushort(h[5]) << 16) | __half_as_ushort(h[4]);
            *(uint4*)(s_a + (nb & 1) * BATCH * 8 + r * 8) =
                make_uint4(p0, p1, p2, 0u);
        }
        __syncthreads();
    }

    // ---- final P3 for last batch ----
    {
        unsigned fp = s_f_u + ((NBATCH - 1) & 1) * (BATCH * DD * 2);
        unsigned ap = s_a_u + ((NBATCH - 1) & 1) * (BATCH * 8 * 2);
#pragma unroll
        for (int kc = 0; kc < 4; kc++) {
            unsigned b0, b1;
            ldsm2t(b0, b1, ap + (kc * 16 + (lane & 15)) * 16);
            int row = kc * 16 + trow;
            unsigned rbase = fp + row * 512;
            {
                unsigned a0, a1, a2, a3;
                int ch = w * 2 + tsel;
                ldsm4t(a0, a1, a2, a3, rbase + ((ch ^ (row & 7)) << 4));
                mma16816(u0, a0, a1, a2, a3, b0, b1);
            }
            {
                unsigned a0, a1, a2, a3;
                int ch = (w + 8) * 2 + tsel;
                ldsm4t(a0, a1, a2, a3, rbase + ((ch ^ (row & 7)) << 4));
                mma16816(u1, a0, a1, a2, a3, b0, b1);
            }
        }
    }

    // ---- epilogue: write U tiles and S ----
    {
        float* base = g_partU + (size_t)(b * CHUNKS + chunk) * KK * DD;
        if (t4 < 3) {
            int d0 = w * 16;
            base[(2 * t4) * DD + d0 + g4]         = u0[0];
            base[(2 * t4 + 1) * DD + d0 + g4]     = u0[1];
            base[(2 * t4) * DD + d0 + 8 + g4]     = u0[2];
            base[(2 * t4 + 1) * DD + d0 + 8 + g4] = u0[3];
            int d1 = (w + 8) * 16;
            base[(2 * t4) * DD + d1 + g4]         = u1[0];
            base[(2 * t4 + 1) * DD + d1 + g4]     = u1[1];
            base[(2 * t4) * DD + d1 + 8 + g4]     = u1[2];
            base[(2 * t4 + 1) * DD + d1 + 8 + g4] = u1[3];
        }
    }
    if (tid < 64) {
#pragma unroll
        for (int off = 16; off > 0; off >>= 1)
#pragma unroll
            for (int k = 0; k < KK; k++)
                accS[k] += __shfl_xor_sync(0xFFFFFFFFu, accS[k], off);
        if (lane == 0)
#pragma unroll
            for (int k = 0; k < KK; k++) s_Sp[w * KK + k] = accS[k];
    }
    __syncthreads();
    if (tid < KK)
        g_partS[(b * CHUNKS + chunk) * KK + tid] = s_Sp[tid] + s_Sp[KK + tid];
}

// ---------------------------------------------------------------------------
// Kernel C: per (b,k): reduce partials -> Wv@U/(S+1e-8) -> GRU -> LN -> MLP
//           -> new slots, then (fused) prep for next iteration. block = 256.
// ---------------------------------------------------------------------------
__global__ void __launch_bounds__(256)
update_kernel(float* __restrict__ slots,
              const float* __restrict__ Wv,
              const float* __restrict__ Wih,
              const float* __restrict__ Whh,
              const float* __restrict__ bih,
              const float* __restrict__ bhh,
              const float* __restrict__ lnm_g,
              const float* __restrict__ lnm_b,
              const float* __restrict__ W1,
              const float* __restrict__ b1,
              const float* __restrict__ W2,
              const float* __restrict__ b2,
              const float* __restrict__ lns_g,
              const float* __restrict__ lns_b,
              const float* __restrict__ Wq,
              const float* __restrict__ Wk,
              int do_prep) {
    int k = blockIdx.x, b = blockIdx.y, t = threadIdx.x;
    __shared__ __align__(16) float U[DD];
    __shared__ __align__(16) float s_xv[HH];
    __shared__ __align__(16) float s_hp[HH];
    __shared__ float s_grz[2 * HH];
    __shared__ float s_gin[HH], s_ghn[HH];
    __shared__ float s_hn[HH];
    __shared__ __align__(16) float s_mm[HH];
    __shared__ __align__(16) float s_m1[2 * HH];
    __shared__ __align__(16) float s_s[HH];
    __shared__ __align__(16) float s_q[HH];
    __shared__ float s_st[4];

    {
        float u = 0.f;
#pragma unroll
        for (int c = 0; c < CHUNKS; c++)
            u += g_partU[((size_t)(b * CHUNKS + c) * KK + k) * DD + t];
        U[t] = u;
    }
    if (t < 32) {
        float S = g_partS[(b * CHUNKS + t) * KK + k];
#pragma unroll
        for (int off = 16; off > 0; off >>= 1)
            S += __shfl_xor_sync(0xFFFFFFFFu, S, off);
        if (t == 0) s_st[0] = 1.f / (S + 1e-8f);
    }
    if (t >= 64 && t < 128) s_hp[t - 64] = slots[(b * KK + k) * HH + (t - 64)];
    __syncthreads();

    {
        int o = t >> 2, q = t & 3;
        const float4* wv = (const float4*)(Wv + o * DD + q * 64);
        const float4* uu = (const float4*)(U + q * 64);
        float a0 = 0.f, a1 = 0.f;
#pragma unroll
        for (int i = 0; i < 16; i++) {
            float4 w4 = wv[i], u4 = uu[i];
            a0 += w4.x * u4.x + w4.z * u4.z;
            a1 += w4.y * u4.y + w4.w * u4.w;
        }
        float acc = a0 + a1;
        acc += __shfl_xor_sync(0xFFFFFFFFu, acc, 1);
        acc += __shfl_xor_sync(0xFFFFFFFFu, acc, 2);
        if (q == 0) s_xv[o] = acc * s_st[0];
    }
    __syncthreads();

    if (t < 192) {
        int gate = t >> 6, idx = t & 63;
        const float4* wi = (const float4*)(Wih + t * HH);
        const float4* wh = (const float4*)(Whh + t * HH);
        const float4* xv4 = (const float4*)s_xv;
        const float4* hp4 = (const float4*)s_hp;
        float gi = bih[t], gh = bhh[t];
#pragma unroll
        for (int i = 0; i < 16; i++) {
            float4 w4 = wi[i], x4 = xv4[i];
            gi += w4.x * x4.x + w4.y * x4.y + w4.z * x4.z + w4.w * x4.w;
            float4 v4 = wh[i], h4 = hp4[i];
            gh += v4.x * h4.x + v4.y * h4.y + v4.z * h4.z + v4.w * h4.w;
        }
        if (gate < 2) s_grz[t] = gi + gh;
        else { s_gin[idx] = gi; s_ghn[idx] = gh; }
    }
    __syncthreads();

    if (t < 64) {
        float r = 1.f / (1.f + __expf(-s_grz[t]));
        float z = 1.f / (1.f + __expf(-s_grz[64 + t]));
        float n = tanhf(s_gin[t] + r * s_ghn[t]);
        s_hn[t] = (1.f - z) * n + z * s_hp[t];
    }
    __syncthreads();
    if (t < 32) {
        float a = s_hn[t], c = s_hn[32 + t];
        float s1 = a + c, s2 = a * a + c * c;
#pragma unroll
        for (int off = 16; off > 0; off >>= 1) {
            s1 += __shfl_xor_sync(0xFFFFFFFFu, s1, off);
            s2 += __shfl_xor_sync(0xFFFFFFFFu, s2, off);
        }
        if (t == 0) {
            float mean = s1 * (1.f / HH);
            float var = s2 * (1.f / HH) - mean * mean;
            s_st[1] = mean;
            s_st[2] = rsqrtf(var + 1e-5f);
        }
    }
    __syncthreads();
    if (t < 64) s_mm[t] = (s_hn[t] - s_st[1]) * s_st[2] * lnm_g[t] + lnm_b[t];
    __syncthreads();

    {
        int o = t >> 1, hf = t & 1;
        const float4* w1 = (const float4*)(W1 + o * HH + hf * 32);
        const float4* mm4 = (const float4*)(s_mm + hf * 32);
        float acc = 0.f;
#pragma unroll
        for (int i = 0; i < 8; i++) {
            float4 w4 = w1[i], m4 = mm4[i];
            acc += w4.x * m4.x + w4.y * m4.y + w4.z * m4.z + w4.w * m4.w;
        }
        acc += __shfl_xor_sync(0xFFFFFFFFu, acc, 1);
        if (hf == 0) s_m1[o] = fmaxf(acc + b1[o], 0.f);
    }
    __syncthreads();

    {
        int o = t >> 2, q = t & 3;
        const float4* w2 = (const float4*)(W2 + o * 2 * HH + q * 32);
        const float4* m14 = (const float4*)(s_m1 + q * 32);
        float acc = 0.f;
#pragma unroll
        for (int i = 0; i < 8; i++) {
            float4 w4 = w2[i], m4 = m14[i];
            acc += w4.x * m4.x + w4.y * m4.y + w4.z * m4.z + w4.w * m4.w;
        }
        acc += __shfl_xor_sync(0xFFFFFFFFu, acc, 1);
        acc += __shfl_xor_sync(0xFFFFFFFFu, acc, 2);
        if (q == 0) {
            float out = s_hn[o] + acc + b2[o];
            slots[(b * KK + k) * HH + o] = out;
            s_s[o] = out;
        }
    }

    if (do_prep) {
        __syncthreads();
        prep_phase(b, k, t, s_s, s_q, s_st, lns_g, lns_b, Wq, Wk);
    }
}

// ---------------------------------------------------------------------------
extern "C" void kernel_launch(void* const* d_in, const int* in_sizes, int n_in,
                              void* d_out, int out_size) {
    const float* features   = (const float*)d_in[0];
    const float* slot_noise = (const float*)d_in[1];
    const float* slot_mu    = (const float*)d_in[2];
    const float* slot_sigma = (const float*)d_in[3];
    const float* ln_feat_g  = (const float*)d_in[4];
    const float* ln_feat_b  = (const float*)d_in[5];
    const float* ln_slot_g  = (const float*)d_in[6];
    const float* ln_slot_b  = (const float*)d_in[7];
    const float* ln_mlp_g   = (const float*)d_in[8];
    const float* ln_mlp_b   = (const float*)d_in[9];
    const float* Wk         = (const float*)d_in[10];
    const float* Wv         = (const float*)d_in[11];
    const float* Wq         = (const float*)d_in[12];
    const float* W_ih       = (const float*)d_in[13];
    const float* W_hh       = (const float*)d_in[14];
    const float* b_ih       = (const float*)d_in[15];
    const float* b_hh       = (const float*)d_in[16];
    const float* mlp_W1     = (const float*)d_in[17];
    const float* mlp_b1     = (const float*)d_in[18];
    const float* mlp_W2     = (const float*)d_in[19];
    const float* mlp_b2     = (const float*)d_in[20];

    float* slots = (float*)d_out;  // [B, K, H] lives in the output buffer

    static int smem_set = 0;
    if (!smem_set) {
        cudaFuncSetAttribute(attn_kernel,
                             cudaFuncAttributeMaxDynamicSharedMemorySize,
                             ATTN_SMEM);
        smem_set = 1;
    }

    dim3 gridSmall(KK, BB);
    dim3 gridA(CHUNKS, BB);

    init_prep_kernel<<<gridSmall, 256>>>(slots, slot_noise, slot_mu, slot_sigma,
                                         ln_slot_g, ln_slot_b, Wq, Wk);
    ln_feat_kernel<<<BB * NN / 16, 256>>>(features, ln_feat_g, ln_feat_b);

    for (int it = 0; it < 3; it++) {
        attn_kernel<<<gridA, 256, ATTN_SMEM>>>();
        update_kernel<<<gridSmall, 256>>>(slots, Wv, W_ih, W_hh, b_ih, b_hh,
                                          ln_mlp_g, ln_mlp_b, mlp_W1, mlp_b1,
                                          mlp_W2, mlp_b2, ln_slot_g, ln_slot_b,
                                          Wq, Wk, it < 2 ? 1 : 0);
    }
}